// round 14
// baseline (speedup 1.0000x reference)
#include <cuda_runtime.h>
#include <cuda_bf16.h>
#include <math.h>
#include <stdint.h>

#define Bn   128
#define HW   49
#define Cc   2048
#define Dh   2048
#define De   128
#define Nrow (Bn*HW)          // 6272
#define NTILE 49              // Nrow/128
#define INV_TAU 5.0f

typedef __nv_bfloat16 bf16;

// ========================= PTX helpers =======================================
__device__ __forceinline__ uint32_t smem_u32(const void* p) {
    uint32_t a;
    asm("{ .reg .u64 t; cvta.to.shared.u64 t, %1; cvt.u32.u64 %0, t; }" : "=r"(a) : "l"(p));
    return a;
}
__device__ __forceinline__ void cp16(uint32_t dst, const void* src) {
    asm volatile("cp.async.cg.shared.global [%0], [%1], 16;" :: "r"(dst), "l"(src));
}
#define CP_COMMIT() asm volatile("cp.async.commit_group;" ::: "memory")
#define CP_WAIT0()  asm volatile("cp.async.wait_group 0;" ::: "memory")
#define LDMX4(r0, r1, r2, r3, addr)                                            \
    asm volatile("ldmatrix.sync.aligned.m8n8.x4.shared.b16 {%0,%1,%2,%3}, [%4];" \
        : "=r"(r0), "=r"(r1), "=r"(r2), "=r"(r3) : "r"(addr))

__device__ __forceinline__ void mma16816(float* c, const uint32_t* a, const uint32_t* b) {
    asm volatile("mma.sync.aligned.m16n8k16.row.col.f32.bf16.bf16.f32 "
        "{%0,%1,%2,%3}, {%4,%5,%6,%7}, {%8,%9}, {%0,%1,%2,%3};"
        : "+f"(c[0]), "+f"(c[1]), "+f"(c[2]), "+f"(c[3])
        : "r"(a[0]), "r"(a[1]), "r"(a[2]), "r"(a[3]), "r"(b[0]), "r"(b[1]));
}

// ========================= scratch buffers ===================================
__device__ __align__(256) bf16 g_Wd1T[(size_t)Dh*Cc];
__device__ __align__(256) bf16 g_mWd1T[(size_t)Dh*Cc];
__device__ __align__(256) bf16 g_Wg1T[(size_t)Dh*Cc];
__device__ __align__(256) bf16 g_mWg1T[(size_t)Dh*Cc];
__device__ __align__(256) bf16 g_Wg2T[De*Dh], g_Wd2T[De*Dh];
__device__ __align__(256) bf16 g_mWg2T[De*Dh], g_mWd2T[De*Dh];
__device__ __align__(256) bf16 g_Aq[(size_t)Nrow*Cc], g_Ak[(size_t)Nrow*Cc];
__device__ __align__(256) bf16 g_pq[Bn*Cc], g_pk[Bn*Cc];
__device__ __align__(256) bf16 g_gh[2*(size_t)Bn*Dh];
__device__ __align__(256) bf16 g_hid[2*(size_t)Nrow*Dh];
__device__ __align__(256) bf16 g_qdm[Nrow*De];
__device__ __align__(256) bf16 g_mt[Nrow*De];
__device__ __align__(256) float g_part[4*(size_t)Nrow*De];   // dense L2 partials (2 heads x 2 k-slabs)
__device__ __align__(256) float g_partG[4*(size_t)Bn*De];    // global L2 partials
__device__ __align__(256) float g_Spart[(size_t)NTILE*Nrow];
__device__ float g_qg[Bn*De], g_kg[Bn*De];
__device__ float g_qd[Nrow*De], g_kd[Nrow*De];
__device__ float g_pos[Nrow], g_lg[Bn], g_ld[Nrow];

// ========================= merged prep (transpose x8 + feat x2) ==============
struct TP { const float* W[8]; bf16* T[8]; };

__global__ void prep_all(TP a, const float* __restrict__ fq, const float* __restrict__ fk,
                         bf16* __restrict__ Aqo, bf16* __restrict__ Ako,
                         bf16* __restrict__ pqo, bf16* __restrict__ pko) {
    __shared__ float sh[32 * 65];              // 8320 B, reused by both paths
    int id = blockIdx.x;
    int tid = threadIdx.x;
    if (id < 1024) {
        // ---- feat_prep: id -> (cblk 0..3, b 0..127, z 0..1) ----
        float4* ps = (float4*)sh;
        int cblk = id & 3, b = (id >> 2) & 127, zz = id >> 9;
        const float* f = zz ? fk : fq;
        bf16* A    = zz ? Ako : Aqo;
        bf16* pool = zz ? pko : pqo;
        int half = tid >> 7;
        int cl = tid & 127;
        int c4 = cblk * 128 + cl;
        const float4* p = (const float4*)(f + (size_t)b * HW * Cc) + c4;
        int i0 = half ? 25 : 0, i1 = half ? 49 : 25;
        float4 s = {0.f, 0.f, 0.f, 0.f};
        for (int i = i0; i < i1; i++) {
            float4 v = p[(size_t)i * (Cc / 4)];
            s.x += v.x; s.y += v.y; s.z += v.z; s.w += v.w;
            __nv_bfloat162 p0, p1;
            p0.x = __float2bfloat16(v.x); p0.y = __float2bfloat16(v.y);
            p1.x = __float2bfloat16(v.z); p1.y = __float2bfloat16(v.w);
            size_t o = ((size_t)b * HW + i) * Cc + c4 * 4;
            *(__nv_bfloat162*)&A[o]     = p0;
            *(__nv_bfloat162*)&A[o + 2] = p1;
        }
        if (half) ps[cl] = s;
        __syncthreads();
        if (!half) {
            float4 s2 = ps[cl];
            s.x += s2.x; s.y += s2.y; s.z += s2.z; s.w += s2.w;
            const float inv = 1.0f / 49.0f;
            __nv_bfloat162 q0, q1;
            q0.x = __float2bfloat16(s.x * inv); q0.y = __float2bfloat16(s.y * inv);
            q1.x = __float2bfloat16(s.z * inv); q1.y = __float2bfloat16(s.w * inv);
            size_t o = (size_t)b * Cc + c4 * 4;
            *(__nv_bfloat162*)&pool[o]     = q0;
            *(__nv_bfloat162*)&pool[o + 2] = q1;
        }
        return;
    }
    // ---- transpose path ----
    id -= 1024;
    float (*t)[65] = (float(*)[65])sh;
    int mat, bx, by, N;
    if (id < 8192) { mat = id >> 11; int r = id & 2047; bx = r & 63; by = r >> 6; N = 2048; }
    else { int i2 = id - 8192; mat = 4 + (i2 >> 7); int r = i2 & 127; bx = r & 3; by = r >> 2; N = 128; }
    const float* W = a.W[mat];
    bf16* T = a.T[mat];
    const int K = 2048;
    int n0 = bx * 32, k0 = by * 64;
    int tx = tid & 31, ty = tid >> 5;
#pragma unroll
    for (int r = 0; r < 64; r += 8)
        t[tx][r + ty] = W[(size_t)(k0 + r + ty) * N + n0 + tx];
    __syncthreads();
#pragma unroll
    for (int j = 0; j < 4; j++) {
        int nl = ty + j * 8;
        __nv_bfloat162 ph;
        ph.x = __float2bfloat16(t[nl][2 * tx]);
        ph.y = __float2bfloat16(t[nl][2 * tx + 1]);
        *(__nv_bfloat162*)&T[(size_t)(n0 + nl) * K + k0 + 2 * tx] = ph;
    }
}

// ========================= op-table mma.sync GEMM (BK=64) ====================
// EPI 0: fp32 partial at op.Cf + kidx*op.M*N (no bias)
// EPI 1: bias+relu -> plain bf16 at op.Cb
// EPI 2: exp-rowsum -> op.Cf[blockIdx.x*op.M + row]
struct GOp { const bf16* A; const bf16* B; const float* bias; float* Cf; bf16* Cb; int M; };
struct GOps { GOp op[4]; };

#define ROWB 144
#define MATB (128*ROWB)         // 18432
#define STGB (2*MATB)           // 36864
#define SM_TOTAL (2*STGB)       // 73728

template<int EPI>
__global__ __launch_bounds__(256, 2)
void gemm_mma(GOps ops, int N, int ldA, int ldB, int nbC, int remC, int nzk, int yglob) {
    extern __shared__ char smem[];
    const uint32_t sb = smem_u32(smem);
    const int tid = threadIdx.x;
    const int wid = tid >> 5;
    const int lid = tid & 31;
    const int wm = wid >> 2;
    const int wn = wid & 3;
    const int g = lid >> 2;
    const int t = lid & 3;
    const int z = blockIdx.z;
    const int head = z / nzk;
    const int kidx = z - head * nzk;
    const bool isg = ((int)blockIdx.y == yglob);
    const GOp op = ops.op[(isg ? 2 : 0) + head];
    const int bm = isg ? 0 : blockIdx.y * 128;
    const int bn = blockIdx.x * 128;
    const int kbeg = (kidx * nbC + min(kidx, remC)) * 64;
    const int nch = nbC + (kidx < remC ? 1 : 0);

    const bf16* A = op.A + (size_t)bm * ldA + kbeg;
    const bf16* B = op.B + (size_t)bn * ldB + kbeg;

    const int r0 = tid >> 3, c0 = tid & 7;

    float acc[4][4][4];
#pragma unroll
    for (int i = 0; i < 4; i++)
#pragma unroll
        for (int j = 0; j < 4; j++)
#pragma unroll
            for (int c = 0; c < 4; c++) acc[i][j][c] = 0.f;

#pragma unroll
    for (int s = 0; s < 4; s++) {
        int r = r0 + s * 32;
        cp16(sb + 0*MATB + r*ROWB + c0*16, A + (size_t)r * ldA + c0 * 8);
        cp16(sb + 1*MATB + r*ROWB + c0*16, B + (size_t)r * ldB + c0 * 8);
    }
    CP_COMMIT();

    const uint32_t a_lm = (uint32_t)((wm*64 + (lid & 7) + ((lid >> 3) & 1) * 8) * ROWB
                                     + ((lid >> 4) & 1) * 16);
    const uint32_t b_lm = (uint32_t)((wn*32 + (lid & 7) + ((lid >> 4) & 1) * 8) * ROWB
                                     + ((lid >> 3) & 1) * 16);

    for (int ch = 0; ch < nch; ch++) {
        CP_WAIT0();
        __syncthreads();
        if (ch + 1 < nch) {
            const int k0 = (ch + 1) * 64;
            uint32_t st = sb + ((ch + 1) & 1) * STGB;
#pragma unroll
            for (int s = 0; s < 4; s++) {
                int r = r0 + s * 32;
                cp16(st + 0*MATB + r*ROWB + c0*16, A + (size_t)r * ldA + k0 + c0 * 8);
                cp16(st + 1*MATB + r*ROWB + c0*16, B + (size_t)r * ldB + k0 + c0 * 8);
            }
            CP_COMMIT();
        }
        const uint32_t st = sb + (ch & 1) * STGB;
#pragma unroll
        for (int ks = 0; ks < 4; ks++) {
            const uint32_t koff = ks * 32;
            uint32_t ah[4][4];
#pragma unroll
            for (int i = 0; i < 4; i++) {
                uint32_t aa = st + a_lm + i * (16 * ROWB) + koff;
                LDMX4(ah[i][0], ah[i][1], ah[i][2], ah[i][3], aa);
            }
#pragma unroll
            for (int jp = 0; jp < 2; jp++) {
                uint32_t bh[2][2];
                uint32_t bb = st + 1*MATB + b_lm + jp * (16 * ROWB) + koff;
                LDMX4(bh[0][0], bh[0][1], bh[1][0], bh[1][1], bb);
#pragma unroll
                for (int i = 0; i < 4; i++)
#pragma unroll
                    for (int jj = 0; jj < 2; jj++)
                        mma16816(acc[i][jp*2 + jj], ah[i], bh[jj]);
            }
        }
        __syncthreads();
    }

    // ---- epilogue ----
    if (EPI == 2) {
        float rs[8];
#pragma unroll
        for (int i = 0; i < 4; i++)
#pragma unroll
            for (int h = 0; h < 2; h++) {
                float s = 0.f;
#pragma unroll
                for (int j = 0; j < 4; j++)
                    s += __expf(acc[i][j][2*h] * INV_TAU)
                       + __expf(acc[i][j][2*h + 1] * INV_TAU);
                s += __shfl_xor_sync(0xFFFFFFFFu, s, 1);
                s += __shfl_xor_sync(0xFFFFFFFFu, s, 2);
                rs[i*2 + h] = s;
            }
        float* sm = (float*)smem;
        __syncthreads();
        if (t == 0) {
#pragma unroll
            for (int idx = 0; idx < 8; idx++) {
                int i = idx >> 1, h = idx & 1;
                int row = wm*64 + i*16 + g + h*8;
                sm[row*4 + wn] = rs[idx];
            }
        }
        __syncthreads();
        if (tid < 128) {
            float tot = sm[tid*4+0] + sm[tid*4+1] + sm[tid*4+2] + sm[tid*4+3];
            op.Cf[(size_t)blockIdx.x * op.M + bm + tid] = tot;
        }
        return;
    }
#pragma unroll
    for (int i = 0; i < 4; i++) {
        int row0 = bm + wm*64 + i*16 + g;
#pragma unroll
        for (int j = 0; j < 4; j++) {
            int col = bn + wn*32 + j*8 + 2*t;
            float b0 = 0.f, b1 = 0.f;
            if (EPI == 1) { b0 = op.bias[col]; b1 = op.bias[col + 1]; }
#pragma unroll
            for (int h = 0; h < 2; h++) {
                int row = row0 + h*8;
                float v0 = acc[i][j][2*h]     + b0;
                float v1 = acc[i][j][2*h + 1] + b1;
                if (EPI == 1) {
                    v0 = fmaxf(v0, 0.f); v1 = fmaxf(v1, 0.f);
                    __nv_bfloat162 ph;
                    ph.x = __float2bfloat16(v0); ph.y = __float2bfloat16(v1);
                    *(__nv_bfloat162*)&op.Cb[(size_t)row * N + col] = ph;
                } else {              // EPI 0: fp32 partial, no bias
                    size_t o = (size_t)kidx * op.M * N + (size_t)row * N + col;
                    float2 fv; fv.x = v0; fv.y = v1;
                    *(float2*)&op.Cf[o] = fv;
                }
            }
        }
    }
}

// ========================= fused reduce + bias + l2norm ======================
// Sums 2 split-K partials, adds bias, normalizes, writes fp32 (+ bf16 for qd).
struct NArgs {
    const float *pd0, *pd1, *pg0, *pg1;          // partial bases (2 slabs each)
    const float *bd2, *mbd2, *bg2, *mbg2;
    float *qg, *kg, *qd, *kd;
    bf16 *qdm;
};

__global__ void l2norm_all(NArgs na) {
    int r = blockIdx.x * 8 + threadIdx.y;
    const float *p0, *p1, *bias;
    float* outx;
    bf16* mo = nullptr;
    if (r < Bn) {
        p0 = na.pg0 + (size_t)r * De; p1 = na.pg0 + (size_t)(Bn + r) * De;
        bias = na.bg2; outx = na.qg + (size_t)r * De;
    } else if (r < 2*Bn) {
        int rr = r - Bn;
        p0 = na.pg1 + (size_t)rr * De; p1 = na.pg1 + (size_t)(Bn + rr) * De;
        bias = na.mbg2; outx = na.kg + (size_t)rr * De;
    } else if (r < 2*Bn + Nrow) {
        int rr = r - 2*Bn;
        p0 = na.pd0 + (size_t)rr * De; p1 = na.pd0 + (size_t)(Nrow + rr) * De;
        bias = na.bd2; outx = na.qd + (size_t)rr * De;
        mo = na.qdm + (size_t)rr * De;
    } else {
        int rr = r - 2*Bn - Nrow;
        p0 = na.pd1 + (size_t)rr * De; p1 = na.pd1 + (size_t)(Nrow + rr) * De;
        bias = na.mbd2; outx = na.kd + (size_t)rr * De;
    }
    int lane = threadIdx.x;
    float4 a = *(const float4*)(p0 + lane * 4);
    float4 b = *(const float4*)(p1 + lane * 4);
    float4 c = *(const float4*)(bias + lane * 4);
    float4 v;
    v.x = a.x + b.x + c.x; v.y = a.y + b.y + c.y;
    v.z = a.z + b.z + c.z; v.w = a.w + b.w + c.w;
    float ss = v.x*v.x + v.y*v.y + v.z*v.z + v.w*v.w;
#pragma unroll
    for (int o = 16; o; o >>= 1) ss += __shfl_xor_sync(0xFFFFFFFFu, ss, o);
    float rr = 1.0f / sqrtf(fmaxf(ss, 1e-12f));
    v.x *= rr; v.y *= rr; v.z *= rr; v.w *= rr;
    *(float4*)(outx + lane * 4) = v;
    if (mo) {
        __nv_bfloat162 p0b, p1b;
        p0b.x = __float2bfloat16(v.x); p0b.y = __float2bfloat16(v.y);
        p1b.x = __float2bfloat16(v.z); p1b.y = __float2bfloat16(v.w);
        *(__nv_bfloat162*)&mo[lane * 4]     = p0b;
        *(__nv_bfloat162*)&mo[lane * 4 + 2] = p1b;
    }
}

// ========================= merged lg + match =================================
__global__ void lg_match(const float* __restrict__ qg, const float* __restrict__ kg,
                         float* __restrict__ lgout,
                         const float* __restrict__ qd, const float* __restrict__ kd,
                         bf16* __restrict__ mt, float* __restrict__ pos) {
    __shared__ float qs[128];
    __shared__ float buf[128];
    __shared__ int s_idx;
    int t = threadIdx.x;
    if (blockIdx.x < Bn) {
        int row = blockIdx.x;
        qs[t] = qg[(size_t)row * De + t];
        __syncthreads();
        const float* kp = kg + (size_t)t * De;
        float dot = 0.f;
#pragma unroll 8
        for (int c = 0; c < De; c++) dot = fmaf(qs[c], kp[c], dot);
        float logit = dot * INV_TAU;
        buf[t] = __expf(logit); __syncthreads();
        for (int s = 64; s; s >>= 1) { if (t < s) buf[t] += buf[t + s]; __syncthreads(); }
        if (t == row) lgout[row] = logf(buf[0]) - logit;
    } else {
        int row = blockIdx.x - Bn;
        int b = row / HW;
        qs[t] = qd[(size_t)row * De + t];
        __syncthreads();
        if (t < HW) {
            const float* kp = kd + (size_t)(b * HW + t) * De;
            float d = 0.f;
#pragma unroll 8
            for (int c = 0; c < De; c++) d = fmaf(qs[c], kp[c], d);
            buf[t] = d;
        }
        __syncthreads();
        if (t == 0) {
            float bv = buf[0]; int bi = 0;
            for (int j = 1; j < HW; j++)
                if (buf[j] > bv) { bv = buf[j]; bi = j; }
            s_idx = bi; pos[row] = bv;
        }
        __syncthreads();
        mt[(size_t)row * De + t] = __float2bfloat16(kd[(size_t)(b * HW + s_idx) * De + t]);
    }
}

__global__ void lse_finish(const float* __restrict__ Spart, const float* __restrict__ pos,
                           float* __restrict__ out) {
    int row = blockIdx.x * 256 + threadIdx.x;
    if (row >= Nrow) return;
    float s = 0.f;
#pragma unroll
    for (int j = 0; j < NTILE; j++) s += Spart[(size_t)j * Nrow + row];
    out[row] = logf(s) - pos[row] * INV_TAU;
}

__global__ void final_kernel(const float* __restrict__ lg, const float* __restrict__ ld,
                             float* __restrict__ out) {
    int t = threadIdx.x;
    float s1 = 0.f, s2 = 0.f;
    if (t < Bn) s1 = lg[t];
    for (int j = t; j < Nrow; j += 256) s2 += ld[j];
    __shared__ float r1[256], r2[256];
    r1[t] = s1; r2[t] = s2; __syncthreads();
    for (int o = 128; o; o >>= 1) {
        if (t < o) { r1[t] += r1[t + o]; r2[t] += r2[t + o]; }
        __syncthreads();
    }
    if (t == 0) out[0] = 0.5f * (r1[0] / (float)Bn) + 0.5f * (r2[0] / (float)Nrow);
}

// ========================= host orchestration ================================
extern "C" void kernel_launch(void* const* d_in, const int* in_sizes, int n_in,
                              void* d_out, int out_size) {
    const float* feat_q = (const float*)d_in[0];
    const float* feat_k = (const float*)d_in[1];
    const float* Wg1  = (const float*)d_in[2];   const float* bg1 = (const float*)d_in[3];
    const float* Wg2  = (const float*)d_in[4];   const float* bg2 = (const float*)d_in[5];
    const float* Wd1  = (const float*)d_in[6];   const float* bd1 = (const float*)d_in[7];
    const float* Wd2  = (const float*)d_in[8];   const float* bd2 = (const float*)d_in[9];
    const float* mWg1 = (const float*)d_in[10];  const float* mbg1 = (const float*)d_in[11];
    const float* mWg2 = (const float*)d_in[12];  const float* mbg2 = (const float*)d_in[13];
    const float* mWd1 = (const float*)d_in[14];  const float* mbd1 = (const float*)d_in[15];
    const float* mWd2 = (const float*)d_in[16];  const float* mbd2 = (const float*)d_in[17];
    float* out = (float*)d_out;

    cudaFuncSetAttribute(gemm_mma<0>, cudaFuncAttributeMaxDynamicSharedMemorySize, SM_TOTAL);
    cudaFuncSetAttribute(gemm_mma<1>, cudaFuncAttributeMaxDynamicSharedMemorySize, SM_TOTAL);
    cudaFuncSetAttribute(gemm_mma<2>, cudaFuncAttributeMaxDynamicSharedMemorySize, SM_TOTAL);

#define SYM(p, s) cudaGetSymbolAddress((void**)&p, s)
    bf16 *Wd1T, *mWd1T, *Wg1T, *mWg1T, *Wg2T, *Wd2T, *mWg2T, *mWd2T;
    bf16 *Aq, *Ak, *pq, *pk, *gh, *hid, *qdm, *mt;
    float *part, *partG, *Spart, *qg, *kg, *qd, *kd, *pos, *lg, *ld;
    SYM(Wd1T, g_Wd1T); SYM(mWd1T, g_mWd1T); SYM(Wg1T, g_Wg1T); SYM(mWg1T, g_mWg1T);
    SYM(Wg2T, g_Wg2T); SYM(Wd2T, g_Wd2T); SYM(mWg2T, g_mWg2T); SYM(mWd2T, g_mWd2T);
    SYM(Aq, g_Aq); SYM(Ak, g_Ak); SYM(pq, g_pq); SYM(pk, g_pk);
    SYM(gh, g_gh); SYM(hid, g_hid); SYM(qdm, g_qdm); SYM(mt, g_mt);
    SYM(part, g_part); SYM(partG, g_partG); SYM(Spart, g_Spart);
    SYM(qg, g_qg); SYM(kg, g_kg); SYM(qd, g_qd); SYM(kd, g_kd);
    SYM(pos, g_pos); SYM(lg, g_lg); SYM(ld, g_ld);
#undef SYM

    // ---- 1. merged prep: 8 transposes + 2 feat ----
    TP tp;
    tp.W[0] = Wd1;  tp.T[0] = Wd1T;
    tp.W[1] = mWd1; tp.T[1] = mWd1T;
    tp.W[2] = Wg1;  tp.T[2] = Wg1T;
    tp.W[3] = mWg1; tp.T[3] = mWg1T;
    tp.W[4] = Wg2;  tp.T[4] = Wg2T;
    tp.W[5] = Wd2;  tp.T[5] = Wd2T;
    tp.W[6] = mWg2; tp.T[6] = mWg2T;
    tp.W[7] = mWd2; tp.T[7] = mWd2T;
    prep_all<<<1024 + 8704, 256>>>(tp, feat_q, feat_k, Aq, Ak, pq, pk);

    // ---- 2. L1 merged: dense (y<49) + global (y==49), full-K, bias+relu bf16 ----
    {
        GOps o;
        o.op[0] = { Aq, Wd1T,  bd1,  nullptr, hid,                   Nrow };
        o.op[1] = { Ak, mWd1T, mbd1, nullptr, hid + (size_t)Nrow*Dh, Nrow };
        o.op[2] = { pq, Wg1T,  bg1,  nullptr, gh,                    Bn };
        o.op[3] = { pk, mWg1T, mbg1, nullptr, gh + (size_t)Bn*Dh,    Bn };
        gemm_mma<1><<<dim3(Dh/128, NTILE + 1, 2), 256, SM_TOTAL>>>(
            o, Dh, Cc, Cc, 32, 0, 1, NTILE);
    }

    // ---- 3. L2 merged: down-proj + global L2, split-K 2 (partials) ----
    {
        GOps o;
        o.op[0] = { hid,                   Wd2T,  nullptr, part,                       nullptr, Nrow };
        o.op[1] = { hid + (size_t)Nrow*Dh, mWd2T, nullptr, part + 2*(size_t)Nrow*De,   nullptr, Nrow };
        o.op[2] = { gh,                    Wg2T,  nullptr, partG,                      nullptr, Bn };
        o.op[3] = { gh + (size_t)Bn*Dh,    mWg2T, nullptr, partG + 2*(size_t)Bn*De,    nullptr, Bn };
        gemm_mma<0><<<dim3(1, NTILE + 1, 4), 256, SM_TOTAL>>>(
            o, De, Dh, Dh, 16, 0, 2, NTILE);
    }

    // ---- 4. fused reduce + bias + l2norm ----
    {
        NArgs na;
        na.pd0 = part;  na.pd1 = part + 2*(size_t)Nrow*De;
        na.pg0 = partG; na.pg1 = partG + 2*(size_t)Bn*De;
        na.bd2 = bd2; na.mbd2 = mbd2; na.bg2 = bg2; na.mbg2 = mbg2;
        na.qg = qg; na.kg = kg; na.qd = qd; na.kd = kd; na.qdm = qdm;
        l2norm_all<<<(2*Bn + 2*Nrow)/8, dim3(32, 8)>>>(na);
    }

    // ---- 5. merged lg + match ----
    lg_match<<<Bn + Nrow, 128>>>(qg, kg, lg, qd, kd, mt, pos);

    // ---- 6. S-GEMM with fused exp epilogue (K=128 -> 2 chunks) ----
    {
        GOps o;
        o.op[0] = { qdm, mt, nullptr, Spart, nullptr, Nrow };
        o.op[1] = o.op[0]; o.op[2] = o.op[0]; o.op[3] = o.op[0];
        gemm_mma<2><<<dim3(NTILE, NTILE, 1), 256, SM_TOTAL>>>(
            o, Nrow, De, De, 2, 0, 1, -1);
    }

    // ---- 7/8. finish ----
    lse_finish<<<(Nrow + 255)/256, 256>>>(Spart, pos, ld);
    final_kernel<<<1, 256>>>(lg, ld, out);
}

// round 15
// speedup vs baseline: 1.5177x; 1.5177x over previous
#include <cuda_runtime.h>
#include <cuda_bf16.h>
#include <math.h>
#include <stdint.h>

#define Bn   128
#define HW   49
#define Cc   2048
#define Dh   2048
#define De   128
#define Nrow (Bn*HW)          // 6272
#define NTILE 49              // Nrow/128
#define INV_TAU 5.0f

typedef __nv_bfloat16 bf16;

// ========================= PTX helpers =======================================
__device__ __forceinline__ uint32_t smem_u32(const void* p) {
    uint32_t a;
    asm("{ .reg .u64 t; cvta.to.shared.u64 t, %1; cvt.u32.u64 %0, t; }" : "=r"(a) : "l"(p));
    return a;
}
__device__ __forceinline__ void cp16(uint32_t dst, const void* src) {
    asm volatile("cp.async.cg.shared.global [%0], [%1], 16;" :: "r"(dst), "l"(src));
}
#define CP_COMMIT() asm volatile("cp.async.commit_group;" ::: "memory")
#define CP_WAIT0()  asm volatile("cp.async.wait_group 0;" ::: "memory")
#define LDMX4(r0, r1, r2, r3, addr)                                            \
    asm volatile("ldmatrix.sync.aligned.m8n8.x4.shared.b16 {%0,%1,%2,%3}, [%4];" \
        : "=r"(r0), "=r"(r1), "=r"(r2), "=r"(r3) : "r"(addr))

__device__ __forceinline__ void mma16816(float* c, const uint32_t* a, const uint32_t* b) {
    asm volatile("mma.sync.aligned.m16n8k16.row.col.f32.bf16.bf16.f32 "
        "{%0,%1,%2,%3}, {%4,%5,%6,%7}, {%8,%9}, {%0,%1,%2,%3};"
        : "+f"(c[0]), "+f"(c[1]), "+f"(c[2]), "+f"(c[3])
        : "r"(a[0]), "r"(a[1]), "r"(a[2]), "r"(a[3]), "r"(b[0]), "r"(b[1]));
}

// ========================= scratch buffers ===================================
__device__ __align__(256) bf16 g_Wd1T[(size_t)Dh*Cc];
__device__ __align__(256) bf16 g_mWd1T[(size_t)Dh*Cc];
__device__ __align__(256) bf16 g_Wg1T[(size_t)Dh*Cc];
__device__ __align__(256) bf16 g_mWg1T[(size_t)Dh*Cc];
__device__ __align__(256) bf16 g_Wg2T[De*Dh], g_Wd2T[De*Dh];
__device__ __align__(256) bf16 g_mWg2T[De*Dh], g_mWd2T[De*Dh];
__device__ __align__(256) bf16 g_Aq[(size_t)Nrow*Cc], g_Ak[(size_t)Nrow*Cc];
__device__ __align__(256) bf16 g_pq[Bn*Cc], g_pk[Bn*Cc];
__device__ __align__(256) bf16 g_gh[2*(size_t)Bn*Dh];
__device__ __align__(256) bf16 g_hid[2*(size_t)Nrow*Dh];
__device__ __align__(256) bf16 g_qdm[Nrow*De];
__device__ __align__(256) bf16 g_mt[Nrow*De];
__device__ __align__(256) float g_Spart[(size_t)NTILE*Nrow];
__device__ float g_qg[Bn*De], g_kg[Bn*De];
__device__ float g_qd[Nrow*De], g_kd[Nrow*De];
__device__ float g_pos[Nrow], g_lg[Bn], g_ld[Nrow];

// ========================= pre-pass kernels ==================================
struct TP { const float* W[8]; bf16* T[8]; };

__global__ void transpose_all(TP a) {
    __shared__ float t[32][65];
    int id = blockIdx.x;
    int mat, bx, by, N;
    if (id < 8192) { mat = id >> 11; int r = id & 2047; bx = r & 63; by = r >> 6; N = 2048; }
    else { int i2 = id - 8192; mat = 4 + (i2 >> 7); int r = i2 & 127; bx = r & 3; by = r >> 2; N = 128; }
    const float* W = a.W[mat];
    bf16* T = a.T[mat];
    const int K = 2048;
    int n0 = bx * 32, k0 = by * 64;
    int tx = threadIdx.x, ty = threadIdx.y;
#pragma unroll
    for (int r = 0; r < 64; r += 8)
        t[tx][r + ty] = W[(size_t)(k0 + r + ty) * N + n0 + tx];
    __syncthreads();
#pragma unroll
    for (int j = 0; j < 4; j++) {
        int nl = ty + j * 8;
        __nv_bfloat162 ph;
        ph.x = __float2bfloat16(t[nl][2 * tx]);
        ph.y = __float2bfloat16(t[nl][2 * tx + 1]);
        *(__nv_bfloat162*)&T[(size_t)(n0 + nl) * K + k0 + 2 * tx] = ph;
    }
}

// fused q+k: per-pixel bf16 convert + mean-pool; HW split across two half-warpsets
__global__ void feat_prep(const float* __restrict__ fq, const float* __restrict__ fk,
                          bf16* __restrict__ Aqo, bf16* __restrict__ Ako,
                          bf16* __restrict__ pqo, bf16* __restrict__ pko) {
    __shared__ float4 ps[128];
    const float* f = blockIdx.z ? fk : fq;
    bf16* A    = blockIdx.z ? Ako : Aqo;
    bf16* pool = blockIdx.z ? pko : pqo;
    int b = blockIdx.y;
    int half = threadIdx.x >> 7;                   // 0 or 1
    int cl = threadIdx.x & 127;
    int c4 = blockIdx.x * 128 + cl;                // 0..511
    const float4* p = (const float4*)(f + (size_t)b * HW * Cc) + c4;
    int i0 = half ? 25 : 0, i1 = half ? 49 : 25;
    float4 s = {0.f, 0.f, 0.f, 0.f};
    for (int i = i0; i < i1; i++) {
        float4 v = p[(size_t)i * (Cc / 4)];
        s.x += v.x; s.y += v.y; s.z += v.z; s.w += v.w;
        __nv_bfloat162 p0, p1;
        p0.x = __float2bfloat16(v.x); p0.y = __float2bfloat16(v.y);
        p1.x = __float2bfloat16(v.z); p1.y = __float2bfloat16(v.w);
        size_t o = ((size_t)b * HW + i) * Cc + c4 * 4;
        *(__nv_bfloat162*)&A[o]     = p0;
        *(__nv_bfloat162*)&A[o + 2] = p1;
    }
    if (half) ps[cl] = s;
    __syncthreads();
    if (!half) {
        float4 s2 = ps[cl];
        s.x += s2.x; s.y += s2.y; s.z += s2.z; s.w += s2.w;
        const float inv = 1.0f / 49.0f;
        __nv_bfloat162 q0, q1;
        q0.x = __float2bfloat16(s.x * inv); q0.y = __float2bfloat16(s.y * inv);
        q1.x = __float2bfloat16(s.z * inv); q1.y = __float2bfloat16(s.w * inv);
        size_t o = (size_t)b * Cc + c4 * 4;
        *(__nv_bfloat162*)&pool[o]     = q0;
        *(__nv_bfloat162*)&pool[o + 2] = q1;
    }
}

// ========================= op-table mma.sync GEMM (BK=64) ====================
// EPI 1: bias+relu -> plain bf16 at op.Cb
// EPI 2: exp-rowsum -> op.Cf[blockIdx.x*op.M + row]
// EPI 3: bias -> fp32 at op.Cf
struct GOp { const bf16* A; const bf16* B; const float* bias; float* Cf; bf16* Cb; int M; };
struct GOps { GOp op[4]; };

#define ROWB 144
#define MATB (128*ROWB)         // 18432
#define STGB (2*MATB)           // 36864
#define SM_TOTAL (2*STGB)       // 73728

template<int EPI>
__global__ __launch_bounds__(256, 2)
void gemm_mma(GOps ops, int N, int ldA, int ldB, int nbC, int remC, int nzk, int yglob) {
    extern __shared__ char smem[];
    const uint32_t sb = smem_u32(smem);
    const int tid = threadIdx.x;
    const int wid = tid >> 5;
    const int lid = tid & 31;
    const int wm = wid >> 2;
    const int wn = wid & 3;
    const int g = lid >> 2;
    const int t = lid & 3;
    const int z = blockIdx.z;
    const int head = z / nzk;
    const int kidx = z - head * nzk;
    const bool isg = ((int)blockIdx.y == yglob);
    const GOp op = ops.op[(isg ? 2 : 0) + head];
    const int bm = isg ? 0 : blockIdx.y * 128;
    const int bn = blockIdx.x * 128;
    const int kbeg = (kidx * nbC + min(kidx, remC)) * 64;
    const int nch = nbC + (kidx < remC ? 1 : 0);

    const bf16* A = op.A + (size_t)bm * ldA + kbeg;
    const bf16* B = op.B + (size_t)bn * ldB + kbeg;

    const int r0 = tid >> 3, c0 = tid & 7;

    float acc[4][4][4];
#pragma unroll
    for (int i = 0; i < 4; i++)
#pragma unroll
        for (int j = 0; j < 4; j++)
#pragma unroll
            for (int c = 0; c < 4; c++) acc[i][j][c] = 0.f;

    // prologue: chunk 0 -> stage 0
#pragma unroll
    for (int s = 0; s < 4; s++) {
        int r = r0 + s * 32;
        cp16(sb + 0*MATB + r*ROWB + c0*16, A + (size_t)r * ldA + c0 * 8);
        cp16(sb + 1*MATB + r*ROWB + c0*16, B + (size_t)r * ldB + c0 * 8);
    }
    CP_COMMIT();

    const uint32_t a_lm = (uint32_t)((wm*64 + (lid & 7) + ((lid >> 3) & 1) * 8) * ROWB
                                     + ((lid >> 4) & 1) * 16);
    const uint32_t b_lm = (uint32_t)((wn*32 + (lid & 7) + ((lid >> 4) & 1) * 8) * ROWB
                                     + ((lid >> 3) & 1) * 16);

    for (int ch = 0; ch < nch; ch++) {
        CP_WAIT0();
        __syncthreads();
        if (ch + 1 < nch) {
            const int k0 = (ch + 1) * 64;
            uint32_t st = sb + ((ch + 1) & 1) * STGB;
#pragma unroll
            for (int s = 0; s < 4; s++) {
                int r = r0 + s * 32;
                cp16(st + 0*MATB + r*ROWB + c0*16, A + (size_t)r * ldA + k0 + c0 * 8);
                cp16(st + 1*MATB + r*ROWB + c0*16, B + (size_t)r * ldB + k0 + c0 * 8);
            }
            CP_COMMIT();
        }
        const uint32_t st = sb + (ch & 1) * STGB;
#pragma unroll
        for (int ks = 0; ks < 4; ks++) {
            const uint32_t koff = ks * 32;
            uint32_t ah[4][4];
#pragma unroll
            for (int i = 0; i < 4; i++) {
                uint32_t aa = st + a_lm + i * (16 * ROWB) + koff;
                LDMX4(ah[i][0], ah[i][1], ah[i][2], ah[i][3], aa);
            }
#pragma unroll
            for (int jp = 0; jp < 2; jp++) {
                uint32_t bh[2][2];
                uint32_t bb = st + 1*MATB + b_lm + jp * (16 * ROWB) + koff;
                LDMX4(bh[0][0], bh[0][1], bh[1][0], bh[1][1], bb);
#pragma unroll
                for (int i = 0; i < 4; i++)
#pragma unroll
                    for (int jj = 0; jj < 2; jj++)
                        mma16816(acc[i][jp*2 + jj], ah[i], bh[jj]);
            }
        }
        __syncthreads();
    }

    // ---- epilogue ----
    if (EPI == 2) {
        float rs[8];
#pragma unroll
        for (int i = 0; i < 4; i++)
#pragma unroll
            for (int h = 0; h < 2; h++) {
                float s = 0.f;
#pragma unroll
                for (int j = 0; j < 4; j++)
                    s += __expf(acc[i][j][2*h] * INV_TAU)
                       + __expf(acc[i][j][2*h + 1] * INV_TAU);
                s += __shfl_xor_sync(0xFFFFFFFFu, s, 1);
                s += __shfl_xor_sync(0xFFFFFFFFu, s, 2);
                rs[i*2 + h] = s;
            }
        float* sm = (float*)smem;
        __syncthreads();
        if (t == 0) {
#pragma unroll
            for (int idx = 0; idx < 8; idx++) {
                int i = idx >> 1, h = idx & 1;
                int row = wm*64 + i*16 + g + h*8;
                sm[row*4 + wn] = rs[idx];
            }
        }
        __syncthreads();
        if (tid < 128) {
            float tot = sm[tid*4+0] + sm[tid*4+1] + sm[tid*4+2] + sm[tid*4+3];
            op.Cf[(size_t)blockIdx.x * op.M + bm + tid] = tot;
        }
        return;
    }
#pragma unroll
    for (int i = 0; i < 4; i++) {
        int row0 = bm + wm*64 + i*16 + g;
#pragma unroll
        for (int j = 0; j < 4; j++) {
            int col = bn + wn*32 + j*8 + 2*t;
            float b0 = op.bias[col], b1 = op.bias[col + 1];
#pragma unroll
            for (int h = 0; h < 2; h++) {
                int row = row0 + h*8;
                float v0 = acc[i][j][2*h]     + b0;
                float v1 = acc[i][j][2*h + 1] + b1;
                if (EPI == 1) {
                    v0 = fmaxf(v0, 0.f); v1 = fmaxf(v1, 0.f);
                    __nv_bfloat162 ph;
                    ph.x = __float2bfloat16(v0); ph.y = __float2bfloat16(v1);
                    *(__nv_bfloat162*)&op.Cb[(size_t)row * N + col] = ph;
                } else {              // EPI 3: bias, fp32, direct
                    float2 fv; fv.x = v0; fv.y = v1;
                    *(float2*)&op.Cf[(size_t)row * N + col] = fv;
                }
            }
        }
    }
}

// ========================= merged l2norm (qg, kg, qd->qdm, kd) ===============
__global__ void l2norm_all(float* __restrict__ qg, float* __restrict__ kg,
                           float* __restrict__ qd, float* __restrict__ kd,
                           bf16* __restrict__ qdm) {
    int r = blockIdx.x * 8 + threadIdx.y;
    float* x;
    bf16* mo = nullptr;
    if (r < Bn) x = qg + (size_t)r * De;
    else if (r < 2*Bn) x = kg + (size_t)(r - Bn) * De;
    else if (r < 2*Bn + Nrow) {
        int rr = r - 2*Bn;
        x = qd + (size_t)rr * De;
        mo = qdm + (size_t)rr * De;
    } else {
        x = kd + (size_t)(r - 2*Bn - Nrow) * De;
    }
    int lane = threadIdx.x;
    float4 v = *(float4*)(x + lane * 4);
    float ss = v.x*v.x + v.y*v.y + v.z*v.z + v.w*v.w;
#pragma unroll
    for (int o = 16; o; o >>= 1) ss += __shfl_xor_sync(0xFFFFFFFFu, ss, o);
    float rr = 1.0f / sqrtf(fmaxf(ss, 1e-12f));
    v.x *= rr; v.y *= rr; v.z *= rr; v.w *= rr;
    *(float4*)(x + lane * 4) = v;
    if (mo) {
        __nv_bfloat162 p0, p1;
        p0.x = __float2bfloat16(v.x); p0.y = __float2bfloat16(v.y);
        p1.x = __float2bfloat16(v.z); p1.y = __float2bfloat16(v.w);
        *(__nv_bfloat162*)&mo[lane * 4]     = p0;
        *(__nv_bfloat162*)&mo[lane * 4 + 2] = p1;
    }
}

// ========================= merged lg + match =================================
__global__ void lg_match(const float* __restrict__ qg, const float* __restrict__ kg,
                         float* __restrict__ lgout,
                         const float* __restrict__ qd, const float* __restrict__ kd,
                         bf16* __restrict__ mt, float* __restrict__ pos) {
    __shared__ float qs[128];
    __shared__ float buf[128];
    __shared__ int s_idx;
    int t = threadIdx.x;
    if (blockIdx.x < Bn) {
        int row = blockIdx.x;
        qs[t] = qg[(size_t)row * De + t];
        __syncthreads();
        const float* kp = kg + (size_t)t * De;
        float dot = 0.f;
#pragma unroll 8
        for (int c = 0; c < De; c++) dot = fmaf(qs[c], kp[c], dot);
        float logit = dot * INV_TAU;
        buf[t] = __expf(logit); __syncthreads();
        for (int s = 64; s; s >>= 1) { if (t < s) buf[t] += buf[t + s]; __syncthreads(); }
        if (t == row) lgout[row] = logf(buf[0]) - logit;
    } else {
        int row = blockIdx.x - Bn;
        int b = row / HW;
        qs[t] = qd[(size_t)row * De + t];
        __syncthreads();
        if (t < HW) {
            const float* kp = kd + (size_t)(b * HW + t) * De;
            float d = 0.f;
#pragma unroll 8
            for (int c = 0; c < De; c++) d = fmaf(qs[c], kp[c], d);
            buf[t] = d;
        }
        __syncthreads();
        if (t == 0) {
            float bv = buf[0]; int bi = 0;
            for (int j = 1; j < HW; j++)
                if (buf[j] > bv) { bv = buf[j]; bi = j; }
            s_idx = bi; pos[row] = bv;
        }
        __syncthreads();
        mt[(size_t)row * De + t] = __float2bfloat16(kd[(size_t)(b * HW + s_idx) * De + t]);
    }
}

__global__ void lse_finish(const float* __restrict__ Spart, const float* __restrict__ pos,
                           float* __restrict__ out) {
    int row = blockIdx.x * 256 + threadIdx.x;
    if (row >= Nrow) return;
    float s = 0.f;
#pragma unroll
    for (int j = 0; j < NTILE; j++) s += Spart[(size_t)j * Nrow + row];
    out[row] = logf(s) - pos[row] * INV_TAU;
}

__global__ void final_kernel(const float* __restrict__ lg, const float* __restrict__ ld,
                             float* __restrict__ out) {
    int t = threadIdx.x;
    float s1 = 0.f, s2 = 0.f;
    if (t < Bn) s1 = lg[t];
    for (int j = t; j < Nrow; j += 256) s2 += ld[j];
    __shared__ float r1[256], r2[256];
    r1[t] = s1; r2[t] = s2; __syncthreads();
    for (int o = 128; o; o >>= 1) {
        if (t < o) { r1[t] += r1[t + o]; r2[t] += r2[t + o]; }
        __syncthreads();
    }
    if (t == 0) out[0] = 0.5f * (r1[0] / (float)Bn) + 0.5f * (r2[0] / (float)Nrow);
}

// ========================= host orchestration ================================
extern "C" void kernel_launch(void* const* d_in, const int* in_sizes, int n_in,
                              void* d_out, int out_size) {
    const float* feat_q = (const float*)d_in[0];
    const float* feat_k = (const float*)d_in[1];
    const float* Wg1  = (const float*)d_in[2];   const float* bg1 = (const float*)d_in[3];
    const float* Wg2  = (const float*)d_in[4];   const float* bg2 = (const float*)d_in[5];
    const float* Wd1  = (const float*)d_in[6];   const float* bd1 = (const float*)d_in[7];
    const float* Wd2  = (const float*)d_in[8];   const float* bd2 = (const float*)d_in[9];
    const float* mWg1 = (const float*)d_in[10];  const float* mbg1 = (const float*)d_in[11];
    const float* mWg2 = (const float*)d_in[12];  const float* mbg2 = (const float*)d_in[13];
    const float* mWd1 = (const float*)d_in[14];  const float* mbd1 = (const float*)d_in[15];
    const float* mWd2 = (const float*)d_in[16];  const float* mbd2 = (const float*)d_in[17];
    float* out = (float*)d_out;

    cudaFuncSetAttribute(gemm_mma<1>, cudaFuncAttributeMaxDynamicSharedMemorySize, SM_TOTAL);
    cudaFuncSetAttribute(gemm_mma<2>, cudaFuncAttributeMaxDynamicSharedMemorySize, SM_TOTAL);
    cudaFuncSetAttribute(gemm_mma<3>, cudaFuncAttributeMaxDynamicSharedMemorySize, SM_TOTAL);

#define SYM(p, s) cudaGetSymbolAddress((void**)&p, s)
    bf16 *Wd1T, *mWd1T, *Wg1T, *mWg1T, *Wg2T, *Wd2T, *mWg2T, *mWd2T;
    bf16 *Aq, *Ak, *pq, *pk, *gh, *hid, *qdm, *mt;
    float *Spart, *qg, *kg, *qd, *kd, *pos, *lg, *ld;
    SYM(Wd1T, g_Wd1T); SYM(mWd1T, g_mWd1T); SYM(Wg1T, g_Wg1T); SYM(mWg1T, g_mWg1T);
    SYM(Wg2T, g_Wg2T); SYM(Wd2T, g_Wd2T); SYM(mWg2T, g_mWg2T); SYM(mWd2T, g_mWd2T);
    SYM(Aq, g_Aq); SYM(Ak, g_Ak); SYM(pq, g_pq); SYM(pk, g_pk);
    SYM(gh, g_gh); SYM(hid, g_hid); SYM(qdm, g_qdm); SYM(mt, g_mt);
    SYM(Spart, g_Spart);
    SYM(qg, g_qg); SYM(kg, g_kg); SYM(qd, g_qd); SYM(kd, g_kd);
    SYM(pos, g_pos); SYM(lg, g_lg); SYM(ld, g_ld);
#undef SYM

    // ---- 1. all weight transposes ----
    TP tp;
    tp.W[0] = Wd1;  tp.T[0] = Wd1T;
    tp.W[1] = mWd1; tp.T[1] = mWd1T;
    tp.W[2] = Wg1;  tp.T[2] = Wg1T;
    tp.W[3] = mWg1; tp.T[3] = mWg1T;
    tp.W[4] = Wg2;  tp.T[4] = Wg2T;
    tp.W[5] = Wd2;  tp.T[5] = Wd2T;
    tp.W[6] = mWg2; tp.T[6] = mWg2T;
    tp.W[7] = mWd2; tp.T[7] = mWd2T;
    transpose_all<<<8704, dim3(32, 8)>>>(tp);

    // ---- 2. activations (HW-split) ----
    feat_prep<<<dim3(4, Bn, 2), 256>>>(feat_q, feat_k, Aq, Ak, pq, pk);

    // ---- 3. L1 merged: dense (y<49) + global (y==49), full-K, bias+relu bf16 ----
    {
        GOps o;
        o.op[0] = { Aq, Wd1T,  bd1,  nullptr, hid,                   Nrow };
        o.op[1] = { Ak, mWd1T, mbd1, nullptr, hid + (size_t)Nrow*Dh, Nrow };
        o.op[2] = { pq, Wg1T,  bg1,  nullptr, gh,                    Bn };
        o.op[3] = { pk, mWg1T, mbg1, nullptr, gh + (size_t)Bn*Dh,    Bn };
        gemm_mma<1><<<dim3(Dh/128, NTILE + 1, 2), 256, SM_TOTAL>>>(
            o, Dh, Cc, Cc, 32, 0, 1, NTILE);
    }

    // ---- 4. L2 merged: down-proj + global L2, full-K, bias fp32 direct ----
    {
        GOps o;
        o.op[0] = { hid,                   Wd2T,  bd2,  qd, nullptr, Nrow };
        o.op[1] = { hid + (size_t)Nrow*Dh, mWd2T, mbd2, kd, nullptr, Nrow };
        o.op[2] = { gh,                    Wg2T,  bg2,  qg, nullptr, Bn };
        o.op[3] = { gh + (size_t)Bn*Dh,    mWg2T, mbg2, kg, nullptr, Bn };
        gemm_mma<3><<<dim3(1, NTILE + 1, 2), 256, SM_TOTAL>>>(
            o, De, Dh, Dh, 32, 0, 1, NTILE);
    }

    // ---- 5. merged l2norm ----
    l2norm_all<<<(2*Bn + 2*Nrow)/8, dim3(32, 8)>>>(qg, kg, qd, kd, qdm);

    // ---- 6. merged lg + match ----
    lg_match<<<Bn + Nrow, 128>>>(qg, kg, lg, qd, kd, mt, pos);

    // ---- 7. S-GEMM with fused exp epilogue (K=128 -> 2 chunks) ----
    {
        GOps o;
        o.op[0] = { qdm, mt, nullptr, Spart, nullptr, Nrow };
        o.op[1] = o.op[0]; o.op[2] = o.op[0]; o.op[3] = o.op[0];
        gemm_mma<2><<<dim3(NTILE, NTILE, 1), 256, SM_TOTAL>>>(
            o, Nrow, De, De, 2, 0, 1, -1);
    }

    // ---- 8/9. finish ----
    lse_finish<<<(Nrow + 255)/256, 256>>>(Spart, pos, ld);
    final_kernel<<<1, 256>>>(lg, ld, out);
}

// round 16
// speedup vs baseline: 1.5248x; 1.0047x over previous
#include <cuda_runtime.h>
#include <cuda_bf16.h>
#include <math.h>
#include <stdint.h>

#define Bn   128
#define HW   49
#define Cc   2048
#define Dh   2048
#define De   128
#define Nrow (Bn*HW)          // 6272
#define NTILE 49              // Nrow/128
#define INV_TAU 5.0f

typedef __nv_bfloat16 bf16;

// ========================= PTX helpers =======================================
__device__ __forceinline__ uint32_t smem_u32(const void* p) {
    uint32_t a;
    asm("{ .reg .u64 t; cvta.to.shared.u64 t, %1; cvt.u32.u64 %0, t; }" : "=r"(a) : "l"(p));
    return a;
}
__device__ __forceinline__ void cp16(uint32_t dst, const void* src) {
    asm volatile("cp.async.cg.shared.global [%0], [%1], 16;" :: "r"(dst), "l"(src));
}
#define CP_COMMIT() asm volatile("cp.async.commit_group;" ::: "memory")
#define CP_WAIT0()  asm volatile("cp.async.wait_group 0;" ::: "memory")
#define LDMX4(r0, r1, r2, r3, addr)                                            \
    asm volatile("ldmatrix.sync.aligned.m8n8.x4.shared.b16 {%0,%1,%2,%3}, [%4];" \
        : "=r"(r0), "=r"(r1), "=r"(r2), "=r"(r3) : "r"(addr))

__device__ __forceinline__ void mma16816(float* c, const uint32_t* a, const uint32_t* b) {
    asm volatile("mma.sync.aligned.m16n8k16.row.col.f32.bf16.bf16.f32 "
        "{%0,%1,%2,%3}, {%4,%5,%6,%7}, {%8,%9}, {%0,%1,%2,%3};"
        : "+f"(c[0]), "+f"(c[1]), "+f"(c[2]), "+f"(c[3])
        : "r"(a[0]), "r"(a[1]), "r"(a[2]), "r"(a[3]), "r"(b[0]), "r"(b[1]));
}

// ========================= scratch buffers ===================================
__device__ __align__(256) bf16 g_Wd1T[(size_t)Dh*Cc];
__device__ __align__(256) bf16 g_mWd1T[(size_t)Dh*Cc];
__device__ __align__(256) bf16 g_Wg1T[(size_t)Dh*Cc];
__device__ __align__(256) bf16 g_mWg1T[(size_t)Dh*Cc];
__device__ __align__(256) bf16 g_Wg2T[De*Dh], g_Wd2T[De*Dh];
__device__ __align__(256) bf16 g_mWg2T[De*Dh], g_mWd2T[De*Dh];
__device__ __align__(256) bf16 g_Aq[(size_t)Nrow*Cc], g_Ak[(size_t)Nrow*Cc];
__device__ __align__(256) bf16 g_pq[Bn*Cc], g_pk[Bn*Cc];
__device__ __align__(256) bf16 g_gh[2*(size_t)Bn*Dh];
__device__ __align__(256) bf16 g_hid[2*(size_t)Nrow*Dh];
__device__ __align__(256) bf16 g_qdm[Nrow*De];
__device__ __align__(256) bf16 g_mt[Nrow*De];
__device__ __align__(256) float g_part[4*(size_t)Nrow*De];   // 2 heads x 2 k-slabs
__device__ __align__(256) float g_partG[4*(size_t)Bn*De];
__device__ __align__(256) float g_Spart[(size_t)NTILE*Nrow];
__device__ float g_qg[Bn*De], g_kg[Bn*De];
__device__ float g_qd[Nrow*De], g_kd[Nrow*De];
__device__ float g_pos[Nrow], g_lg[Bn], g_ld[Nrow];

// ========================= pre-pass kernels ==================================
struct TP { const float* W[8]; bf16* T[8]; };

__global__ void transpose_all(TP a) {
    __shared__ float t[32][65];
    int id = blockIdx.x;
    int mat, bx, by, N;
    if (id < 8192) { mat = id >> 11; int r = id & 2047; bx = r & 63; by = r >> 6; N = 2048; }
    else { int i2 = id - 8192; mat = 4 + (i2 >> 7); int r = i2 & 127; bx = r & 3; by = r >> 2; N = 128; }
    const float* W = a.W[mat];
    bf16* T = a.T[mat];
    const int K = 2048;
    int n0 = bx * 32, k0 = by * 64;
    int tx = threadIdx.x, ty = threadIdx.y;
#pragma unroll
    for (int r = 0; r < 64; r += 8)
        t[tx][r + ty] = W[(size_t)(k0 + r + ty) * N + n0 + tx];
    __syncthreads();
#pragma unroll
    for (int j = 0; j < 4; j++) {
        int nl = ty + j * 8;
        __nv_bfloat162 ph;
        ph.x = __float2bfloat16(t[nl][2 * tx]);
        ph.y = __float2bfloat16(t[nl][2 * tx + 1]);
        *(__nv_bfloat162*)&T[(size_t)(n0 + nl) * K + k0 + 2 * tx] = ph;
    }
}

// fused q+k: per-pixel bf16 convert + mean-pool; HW split across two half-warpsets
__global__ void feat_prep(const float* __restrict__ fq, const float* __restrict__ fk,
                          bf16* __restrict__ Aqo, bf16* __restrict__ Ako,
                          bf16* __restrict__ pqo, bf16* __restrict__ pko) {
    __shared__ float4 ps[128];
    const float* f = blockIdx.z ? fk : fq;
    bf16* A    = blockIdx.z ? Ako : Aqo;
    bf16* pool = blockIdx.z ? pko : pqo;
    int b = blockIdx.y;
    int half = threadIdx.x >> 7;                   // 0 or 1
    int cl = threadIdx.x & 127;
    int c4 = blockIdx.x * 128 + cl;                // 0..511
    const float4* p = (const float4*)(f + (size_t)b * HW * Cc) + c4;
    int i0 = half ? 25 : 0, i1 = half ? 49 : 25;
    float4 s = {0.f, 0.f, 0.f, 0.f};
    for (int i = i0; i < i1; i++) {
        float4 v = p[(size_t)i * (Cc / 4)];
        s.x += v.x; s.y += v.y; s.z += v.z; s.w += v.w;
        __nv_bfloat162 p0, p1;
        p0.x = __float2bfloat16(v.x); p0.y = __float2bfloat16(v.y);
        p1.x = __float2bfloat16(v.z); p1.y = __float2bfloat16(v.w);
        size_t o = ((size_t)b * HW + i) * Cc + c4 * 4;
        *(__nv_bfloat162*)&A[o]     = p0;
        *(__nv_bfloat162*)&A[o + 2] = p1;
    }
    if (half) ps[cl] = s;
    __syncthreads();
    if (!half) {
        float4 s2 = ps[cl];
        s.x += s2.x; s.y += s2.y; s.z += s2.z; s.w += s2.w;
        const float inv = 1.0f / 49.0f;
        __nv_bfloat162 q0, q1;
        q0.x = __float2bfloat16(s.x * inv); q0.y = __float2bfloat16(s.y * inv);
        q1.x = __float2bfloat16(s.z * inv); q1.y = __float2bfloat16(s.w * inv);
        size_t o = (size_t)b * Cc + c4 * 4;
        *(__nv_bfloat162*)&pool[o]     = q0;
        *(__nv_bfloat162*)&pool[o + 2] = q1;
    }
}

// ========================= op-table mma.sync GEMM (BK=64) ====================
// EPI 0: fp32 partial at op.Cf + kidx*op.M*N (no bias)
// EPI 1: bias+relu -> plain bf16 at op.Cb
// EPI 2: exp-rowsum -> op.Cf[blockIdx.x*op.M + row]
struct GOp { const bf16* A; const bf16* B; const float* bias; float* Cf; bf16* Cb; int M; };
struct GOps { GOp op[4]; };

#define ROWB 144
#define MATB (128*ROWB)         // 18432
#define STGB (2*MATB)           // 36864
#define SM_TOTAL (2*STGB)       // 73728

template<int EPI>
__global__ __launch_bounds__(256, 2)
void gemm_mma(GOps ops, int N, int ldA, int ldB, int nbC, int remC, int nzk, int yglob) {
    extern __shared__ char smem[];
    const uint32_t sb = smem_u32(smem);
    const int tid = threadIdx.x;
    const int wid = tid >> 5;
    const int lid = tid & 31;
    const int wm = wid >> 2;
    const int wn = wid & 3;
    const int g = lid >> 2;
    const int t = lid & 3;
    const int z = blockIdx.z;
    const int head = z / nzk;
    const int kidx = z - head * nzk;
    const bool isg = ((int)blockIdx.y == yglob);
    const GOp op = ops.op[(isg ? 2 : 0) + head];
    const int bm = isg ? 0 : blockIdx.y * 128;
    const int bn = blockIdx.x * 128;
    const int kbeg = (kidx * nbC + min(kidx, remC)) * 64;
    const int nch = nbC + (kidx < remC ? 1 : 0);

    const bf16* A = op.A + (size_t)bm * ldA + kbeg;
    const bf16* B = op.B + (size_t)bn * ldB + kbeg;

    const int r0 = tid >> 3, c0 = tid & 7;

    float acc[4][4][4];
#pragma unroll
    for (int i = 0; i < 4; i++)
#pragma unroll
        for (int j = 0; j < 4; j++)
#pragma unroll
            for (int c = 0; c < 4; c++) acc[i][j][c] = 0.f;

    // prologue: chunk 0 -> stage 0
#pragma unroll
    for (int s = 0; s < 4; s++) {
        int r = r0 + s * 32;
        cp16(sb + 0*MATB + r*ROWB + c0*16, A + (size_t)r * ldA + c0 * 8);
        cp16(sb + 1*MATB + r*ROWB + c0*16, B + (size_t)r * ldB + c0 * 8);
    }
    CP_COMMIT();

    const uint32_t a_lm = (uint32_t)((wm*64 + (lid & 7) + ((lid >> 3) & 1) * 8) * ROWB
                                     + ((lid >> 4) & 1) * 16);
    const uint32_t b_lm = (uint32_t)((wn*32 + (lid & 7) + ((lid >> 4) & 1) * 8) * ROWB
                                     + ((lid >> 3) & 1) * 16);

    for (int ch = 0; ch < nch; ch++) {
        CP_WAIT0();
        __syncthreads();
        if (ch + 1 < nch) {
            const int k0 = (ch + 1) * 64;
            uint32_t st = sb + ((ch + 1) & 1) * STGB;
#pragma unroll
            for (int s = 0; s < 4; s++) {
                int r = r0 + s * 32;
                cp16(st + 0*MATB + r*ROWB + c0*16, A + (size_t)r * ldA + k0 + c0 * 8);
                cp16(st + 1*MATB + r*ROWB + c0*16, B + (size_t)r * ldB + k0 + c0 * 8);
            }
            CP_COMMIT();
        }
        const uint32_t st = sb + (ch & 1) * STGB;
#pragma unroll
        for (int ks = 0; ks < 4; ks++) {
            const uint32_t koff = ks * 32;
            uint32_t ah[4][4];
#pragma unroll
            for (int i = 0; i < 4; i++) {
                uint32_t aa = st + a_lm + i * (16 * ROWB) + koff;
                LDMX4(ah[i][0], ah[i][1], ah[i][2], ah[i][3], aa);
            }
#pragma unroll
            for (int jp = 0; jp < 2; jp++) {
                uint32_t bh[2][2];
                uint32_t bb = st + 1*MATB + b_lm + jp * (16 * ROWB) + koff;
                LDMX4(bh[0][0], bh[0][1], bh[1][0], bh[1][1], bb);
#pragma unroll
                for (int i = 0; i < 4; i++)
#pragma unroll
                    for (int jj = 0; jj < 2; jj++)
                        mma16816(acc[i][jp*2 + jj], ah[i], bh[jj]);
            }
        }
        __syncthreads();
    }

    // ---- epilogue ----
    if (EPI == 2) {
        float rs[8];
#pragma unroll
        for (int i = 0; i < 4; i++)
#pragma unroll
            for (int h = 0; h < 2; h++) {
                float s = 0.f;
#pragma unroll
                for (int j = 0; j < 4; j++)
                    s += __expf(acc[i][j][2*h] * INV_TAU)
                       + __expf(acc[i][j][2*h + 1] * INV_TAU);
                s += __shfl_xor_sync(0xFFFFFFFFu, s, 1);
                s += __shfl_xor_sync(0xFFFFFFFFu, s, 2);
                rs[i*2 + h] = s;
            }
        float* sm = (float*)smem;
        __syncthreads();
        if (t == 0) {
#pragma unroll
            for (int idx = 0; idx < 8; idx++) {
                int i = idx >> 1, h = idx & 1;
                int row = wm*64 + i*16 + g + h*8;
                sm[row*4 + wn] = rs[idx];
            }
        }
        __syncthreads();
        if (tid < 128) {
            float tot = sm[tid*4+0] + sm[tid*4+1] + sm[tid*4+2] + sm[tid*4+3];
            op.Cf[(size_t)blockIdx.x * op.M + bm + tid] = tot;
        }
        return;
    }
#pragma unroll
    for (int i = 0; i < 4; i++) {
        int row0 = bm + wm*64 + i*16 + g;
#pragma unroll
        for (int j = 0; j < 4; j++) {
            int col = bn + wn*32 + j*8 + 2*t;
            float b0 = 0.f, b1 = 0.f;
            if (EPI == 1) { b0 = op.bias[col]; b1 = op.bias[col + 1]; }
#pragma unroll
            for (int h = 0; h < 2; h++) {
                int row = row0 + h*8;
                float v0 = acc[i][j][2*h]     + b0;
                float v1 = acc[i][j][2*h + 1] + b1;
                if (EPI == 1) {
                    v0 = fmaxf(v0, 0.f); v1 = fmaxf(v1, 0.f);
                    __nv_bfloat162 ph;
                    ph.x = __float2bfloat16(v0); ph.y = __float2bfloat16(v1);
                    *(__nv_bfloat162*)&op.Cb[(size_t)row * N + col] = ph;
                } else {              // EPI 0: fp32 partial at + kidx*M*N
                    size_t o = (size_t)kidx * op.M * N + (size_t)row * N + col;
                    float2 fv; fv.x = v0; fv.y = v1;
                    *(float2*)&op.Cf[o] = fv;
                }
            }
        }
    }
}

// ========================= fused reduce + bias + l2norm ======================
struct NArgs {
    const float *pd0, *pd1, *pg0, *pg1;
    const float *bd2, *mbd2, *bg2, *mbg2;
    float *qg, *kg, *qd, *kd;
    bf16 *qdm;
};

__global__ void l2norm_all(NArgs na) {
    int r = blockIdx.x * 8 + threadIdx.y;
    const float *p0, *p1, *bias;
    float* outx;
    bf16* mo = nullptr;
    if (r < Bn) {
        p0 = na.pg0 + (size_t)r * De; p1 = na.pg0 + (size_t)(Bn + r) * De;
        bias = na.bg2; outx = na.qg + (size_t)r * De;
    } else if (r < 2*Bn) {
        int rr = r - Bn;
        p0 = na.pg1 + (size_t)rr * De; p1 = na.pg1 + (size_t)(Bn + rr) * De;
        bias = na.mbg2; outx = na.kg + (size_t)rr * De;
    } else if (r < 2*Bn + Nrow) {
        int rr = r - 2*Bn;
        p0 = na.pd0 + (size_t)rr * De; p1 = na.pd0 + (size_t)(Nrow + rr) * De;
        bias = na.bd2; outx = na.qd + (size_t)rr * De;
        mo = na.qdm + (size_t)rr * De;
    } else {
        int rr = r - 2*Bn - Nrow;
        p0 = na.pd1 + (size_t)rr * De; p1 = na.pd1 + (size_t)(Nrow + rr) * De;
        bias = na.mbd2; outx = na.kd + (size_t)rr * De;
    }
    int lane = threadIdx.x;
    float4 a = *(const float4*)(p0 + lane * 4);
    float4 b = *(const float4*)(p1 + lane * 4);
    float4 c = *(const float4*)(bias + lane * 4);
    float4 v;
    v.x = a.x + b.x + c.x; v.y = a.y + b.y + c.y;
    v.z = a.z + b.z + c.z; v.w = a.w + b.w + c.w;
    float ss = v.x*v.x + v.y*v.y + v.z*v.z + v.w*v.w;
#pragma unroll
    for (int o = 16; o; o >>= 1) ss += __shfl_xor_sync(0xFFFFFFFFu, ss, o);
    float rr = 1.0f / sqrtf(fmaxf(ss, 1e-12f));
    v.x *= rr; v.y *= rr; v.z *= rr; v.w *= rr;
    *(float4*)(outx + lane * 4) = v;
    if (mo) {
        __nv_bfloat162 p0b, p1b;
        p0b.x = __float2bfloat16(v.x); p0b.y = __float2bfloat16(v.y);
        p1b.x = __float2bfloat16(v.z); p1b.y = __float2bfloat16(v.w);
        *(__nv_bfloat162*)&mo[lane * 4]     = p0b;
        *(__nv_bfloat162*)&mo[lane * 4 + 2] = p1b;
    }
}

// ========================= merged lg + match =================================
__global__ void lg_match(const float* __restrict__ qg, const float* __restrict__ kg,
                         float* __restrict__ lgout,
                         const float* __restrict__ qd, const float* __restrict__ kd,
                         bf16* __restrict__ mt, float* __restrict__ pos) {
    __shared__ float qs[128];
    __shared__ float buf[128];
    __shared__ int s_idx;
    int t = threadIdx.x;
    if (blockIdx.x < Bn) {
        int row = blockIdx.x;
        qs[t] = qg[(size_t)row * De + t];
        __syncthreads();
        const float* kp = kg + (size_t)t * De;
        float dot = 0.f;
#pragma unroll 8
        for (int c = 0; c < De; c++) dot = fmaf(qs[c], kp[c], dot);
        float logit = dot * INV_TAU;
        buf[t] = __expf(logit); __syncthreads();
        for (int s = 64; s; s >>= 1) { if (t < s) buf[t] += buf[t + s]; __syncthreads(); }
        if (t == row) lgout[row] = logf(buf[0]) - logit;
    } else {
        int row = blockIdx.x - Bn;
        int b = row / HW;
        qs[t] = qd[(size_t)row * De + t];
        __syncthreads();
        if (t < HW) {
            const float* kp = kd + (size_t)(b * HW + t) * De;
            float d = 0.f;
#pragma unroll 8
            for (int c = 0; c < De; c++) d = fmaf(qs[c], kp[c], d);
            buf[t] = d;
        }
        __syncthreads();
        if (t == 0) {
            float bv = buf[0]; int bi = 0;
            for (int j = 1; j < HW; j++)
                if (buf[j] > bv) { bv = buf[j]; bi = j; }
            s_idx = bi; pos[row] = bv;
        }
        __syncthreads();
        mt[(size_t)row * De + t] = __float2bfloat16(kd[(size_t)(b * HW + s_idx) * De + t]);
    }
}

__global__ void lse_finish(const float* __restrict__ Spart, const float* __restrict__ pos,
                           float* __restrict__ out) {
    int row = blockIdx.x * 256 + threadIdx.x;
    if (row >= Nrow) return;
    float s = 0.f;
#pragma unroll
    for (int j = 0; j < NTILE; j++) s += Spart[(size_t)j * Nrow + row];
    out[row] = logf(s) - pos[row] * INV_TAU;
}

__global__ void final_kernel(const float* __restrict__ lg, const float* __restrict__ ld,
                             float* __restrict__ out) {
    int t = threadIdx.x;
    float s1 = 0.f, s2 = 0.f;
    if (t < Bn) s1 = lg[t];
    for (int j = t; j < Nrow; j += 256) s2 += ld[j];
    __shared__ float r1[256], r2[256];
    r1[t] = s1; r2[t] = s2; __syncthreads();
    for (int o = 128; o; o >>= 1) {
        if (t < o) { r1[t] += r1[t + o]; r2[t] += r2[t + o]; }
        __syncthreads();
    }
    if (t == 0) out[0] = 0.5f * (r1[0] / (float)Bn) + 0.5f * (r2[0] / (float)Nrow);
}

// ========================= host orchestration ================================
extern "C" void kernel_launch(void* const* d_in, const int* in_sizes, int n_in,
                              void* d_out, int out_size) {
    const float* feat_q = (const float*)d_in[0];
    const float* feat_k = (const float*)d_in[1];
    const float* Wg1  = (const float*)d_in[2];   const float* bg1 = (const float*)d_in[3];
    const float* Wg2  = (const float*)d_in[4];   const float* bg2 = (const float*)d_in[5];
    const float* Wd1  = (const float*)d_in[6];   const float* bd1 = (const float*)d_in[7];
    const float* Wd2  = (const float*)d_in[8];   const float* bd2 = (const float*)d_in[9];
    const float* mWg1 = (const float*)d_in[10];  const float* mbg1 = (const float*)d_in[11];
    const float* mWg2 = (const float*)d_in[12];  const float* mbg2 = (const float*)d_in[13];
    const float* mWd1 = (const float*)d_in[14];  const float* mbd1 = (const float*)d_in[15];
    const float* mWd2 = (const float*)d_in[16];  const float* mbd2 = (const float*)d_in[17];
    float* out = (float*)d_out;

    cudaFuncSetAttribute(gemm_mma<0>, cudaFuncAttributeMaxDynamicSharedMemorySize, SM_TOTAL);
    cudaFuncSetAttribute(gemm_mma<1>, cudaFuncAttributeMaxDynamicSharedMemorySize, SM_TOTAL);
    cudaFuncSetAttribute(gemm_mma<2>, cudaFuncAttributeMaxDynamicSharedMemorySize, SM_TOTAL);

#define SYM(p, s) cudaGetSymbolAddress((void**)&p, s)
    bf16 *Wd1T, *mWd1T, *Wg1T, *mWg1T, *Wg2T, *Wd2T, *mWg2T, *mWd2T;
    bf16 *Aq, *Ak, *pq, *pk, *gh, *hid, *qdm, *mt;
    float *part, *partG, *Spart, *qg, *kg, *qd, *kd, *pos, *lg, *ld;
    SYM(Wd1T, g_Wd1T); SYM(mWd1T, g_mWd1T); SYM(Wg1T, g_Wg1T); SYM(mWg1T, g_mWg1T);
    SYM(Wg2T, g_Wg2T); SYM(Wd2T, g_Wd2T); SYM(mWg2T, g_mWg2T); SYM(mWd2T, g_mWd2T);
    SYM(Aq, g_Aq); SYM(Ak, g_Ak); SYM(pq, g_pq); SYM(pk, g_pk);
    SYM(gh, g_gh); SYM(hid, g_hid); SYM(qdm, g_qdm); SYM(mt, g_mt);
    SYM(part, g_part); SYM(partG, g_partG); SYM(Spart, g_Spart);
    SYM(qg, g_qg); SYM(kg, g_kg); SYM(qd, g_qd); SYM(kd, g_kd);
    SYM(pos, g_pos); SYM(lg, g_lg); SYM(ld, g_ld);
#undef SYM

    // ---- 1. all weight transposes ----
    TP tp;
    tp.W[0] = Wd1;  tp.T[0] = Wd1T;
    tp.W[1] = mWd1; tp.T[1] = mWd1T;
    tp.W[2] = Wg1;  tp.T[2] = Wg1T;
    tp.W[3] = mWg1; tp.T[3] = mWg1T;
    tp.W[4] = Wg2;  tp.T[4] = Wg2T;
    tp.W[5] = Wd2;  tp.T[5] = Wd2T;
    tp.W[6] = mWg2; tp.T[6] = mWg2T;
    tp.W[7] = mWd2; tp.T[7] = mWd2T;
    transpose_all<<<8704, dim3(32, 8)>>>(tp);

    // ---- 2. activations (HW-split) ----
    feat_prep<<<dim3(4, Bn, 2), 256>>>(feat_q, feat_k, Aq, Ak, pq, pk);

    // ---- 3. L1 merged: dense (y<49) + global (y==49), full-K, bias+relu bf16 ----
    {
        GOps o;
        o.op[0] = { Aq, Wd1T,  bd1,  nullptr, hid,                   Nrow };
        o.op[1] = { Ak, mWd1T, mbd1, nullptr, hid + (size_t)Nrow*Dh, Nrow };
        o.op[2] = { pq, Wg1T,  bg1,  nullptr, gh,                    Bn };
        o.op[3] = { pk, mWg1T, mbg1, nullptr, gh + (size_t)Bn*Dh,    Bn };
        gemm_mma<1><<<dim3(Dh/128, NTILE + 1, 2), 256, SM_TOTAL>>>(
            o, Dh, Cc, Cc, 32, 0, 1, NTILE);
    }

    // ---- 4. L2 merged: down-proj + global L2, split-K 2 (partials) ----
    {
        GOps o;
        o.op[0] = { hid,                   Wd2T,  nullptr, part,                     nullptr, Nrow };
        o.op[1] = { hid + (size_t)Nrow*Dh, mWd2T, nullptr, part + 2*(size_t)Nrow*De, nullptr, Nrow };
        o.op[2] = { gh,                    Wg2T,  nullptr, partG,                    nullptr, Bn };
        o.op[3] = { gh + (size_t)Bn*Dh,    mWg2T, nullptr, partG + 2*(size_t)Bn*De,  nullptr, Bn };
        gemm_mma<0><<<dim3(1, NTILE + 1, 4), 256, SM_TOTAL>>>(
            o, De, Dh, Dh, 16, 0, 2, NTILE);
    }

    // ---- 5. fused reduce + bias + l2norm ----
    {
        NArgs na;
        na.pd0 = part;  na.pd1 = part + 2*(size_t)Nrow*De;
        na.pg0 = partG; na.pg1 = partG + 2*(size_t)Bn*De;
        na.bd2 = bd2; na.mbd2 = mbd2; na.bg2 = bg2; na.mbg2 = mbg2;
        na.qg = qg; na.kg = kg; na.qd = qd; na.kd = kd; na.qdm = qdm;
        l2norm_all<<<(2*Bn + 2*Nrow)/8, dim3(32, 8)>>>(na);
    }

    // ---- 6. merged lg + match ----
    lg_match<<<Bn + Nrow, 128>>>(qg, kg, lg, qd, kd, mt, pos);

    // ---- 7. S-GEMM with fused exp epilogue (K=128 -> 2 chunks) ----
    {
        GOps o;
        o.op[0] = { qdm, mt, nullptr, Spart, nullptr, Nrow };
        o.op[1] = o.op[0]; o.op[2] = o.op[0]; o.op[3] = o.op[0];
        gemm_mma<2><<<dim3(NTILE, NTILE, 1), 256, SM_TOTAL>>>(
            o, Nrow, De, De, 2, 0, 1, -1);
    }

    // ---- 8/9. finish ----
    lse_finish<<<(Nrow + 255)/256, 256>>>(Spart, pos, ld);
    final_kernel<<<1, 256>>>(lg, ld, out);
}

// round 17
// speedup vs baseline: 1.5389x; 1.0092x over previous
#include <cuda_runtime.h>
#include <cuda_bf16.h>
#include <math.h>
#include <stdint.h>

#define Bn   128
#define HW   49
#define Cc   2048
#define Dh   2048
#define De   128
#define Nrow (Bn*HW)          // 6272
#define NTILE 49              // Nrow/128
#define INV_TAU 5.0f

typedef __nv_bfloat16 bf16;

// ========================= PTX helpers =======================================
__device__ __forceinline__ uint32_t smem_u32(const void* p) {
    uint32_t a;
    asm("{ .reg .u64 t; cvta.to.shared.u64 t, %1; cvt.u32.u64 %0, t; }" : "=r"(a) : "l"(p));
    return a;
}
__device__ __forceinline__ void cp16(uint32_t dst, const void* src) {
    asm volatile("cp.async.cg.shared.global [%0], [%1], 16;" :: "r"(dst), "l"(src));
}
#define CP_COMMIT() asm volatile("cp.async.commit_group;" ::: "memory")
#define CP_WAIT0()  asm volatile("cp.async.wait_group 0;" ::: "memory")
#define LDMX4(r0, r1, r2, r3, addr)                                            \
    asm volatile("ldmatrix.sync.aligned.m8n8.x4.shared.b16 {%0,%1,%2,%3}, [%4];" \
        : "=r"(r0), "=r"(r1), "=r"(r2), "=r"(r3) : "r"(addr))

__device__ __forceinline__ void mma16816(float* c, const uint32_t* a, const uint32_t* b) {
    asm volatile("mma.sync.aligned.m16n8k16.row.col.f32.bf16.bf16.f32 "
        "{%0,%1,%2,%3}, {%4,%5,%6,%7}, {%8,%9}, {%0,%1,%2,%3};"
        : "+f"(c[0]), "+f"(c[1]), "+f"(c[2]), "+f"(c[3])
        : "r"(a[0]), "r"(a[1]), "r"(a[2]), "r"(a[3]), "r"(b[0]), "r"(b[1]));
}

// ========================= scratch buffers ===================================
__device__ __align__(256) bf16 g_Wd1T[(size_t)Dh*Cc];
__device__ __align__(256) bf16 g_mWd1T[(size_t)Dh*Cc];
__device__ __align__(256) bf16 g_Wg1T[(size_t)Dh*Cc];
__device__ __align__(256) bf16 g_mWg1T[(size_t)Dh*Cc];
__device__ __align__(256) bf16 g_Wg2T[De*Dh], g_Wd2T[De*Dh];
__device__ __align__(256) bf16 g_mWg2T[De*Dh], g_mWd2T[De*Dh];
__device__ __align__(256) bf16 g_Aq[(size_t)Nrow*Cc], g_Ak[(size_t)Nrow*Cc];
__device__ __align__(256) bf16 g_pq[Bn*Cc], g_pk[Bn*Cc];
__device__ __align__(256) bf16 g_gh[2*(size_t)Bn*Dh];
__device__ __align__(256) bf16 g_hid[2*(size_t)Nrow*Dh];
__device__ __align__(256) bf16 g_qdm[Nrow*De];
__device__ __align__(256) bf16 g_mt[Nrow*De];
__device__ __align__(256) float g_part[8*(size_t)Nrow*De];   // 2 heads x 4 k-slabs
__device__ __align__(256) float g_partG[8*(size_t)Bn*De];
__device__ __align__(256) float g_Spart[(size_t)NTILE*Nrow];
__device__ float g_qg[Bn*De], g_kg[Bn*De];
__device__ float g_qd[Nrow*De], g_kd[Nrow*De];
__device__ float g_pos[Nrow], g_lg[Bn], g_ld[Nrow];

// ========================= pre-pass kernels ==================================
struct TP { const float* W[8]; bf16* T[8]; };

__global__ void transpose_all(TP a) {
    __shared__ float t[32][65];
    int id = blockIdx.x;
    int mat, bx, by, N;
    if (id < 8192) { mat = id >> 11; int r = id & 2047; bx = r & 63; by = r >> 6; N = 2048; }
    else { int i2 = id - 8192; mat = 4 + (i2 >> 7); int r = i2 & 127; bx = r & 3; by = r >> 2; N = 128; }
    const float* W = a.W[mat];
    bf16* T = a.T[mat];
    const int K = 2048;
    int n0 = bx * 32, k0 = by * 64;
    int tx = threadIdx.x, ty = threadIdx.y;
#pragma unroll
    for (int r = 0; r < 64; r += 8)
        t[tx][r + ty] = W[(size_t)(k0 + r + ty) * N + n0 + tx];
    __syncthreads();
#pragma unroll
    for (int j = 0; j < 4; j++) {
        int nl = ty + j * 8;
        __nv_bfloat162 ph;
        ph.x = __float2bfloat16(t[nl][2 * tx]);
        ph.y = __float2bfloat16(t[nl][2 * tx + 1]);
        *(__nv_bfloat162*)&T[(size_t)(n0 + nl) * K + k0 + 2 * tx] = ph;
    }
}

// fused q+k: per-pixel bf16 convert + mean-pool; HW split across two half-warpsets
__global__ void feat_prep(const float* __restrict__ fq, const float* __restrict__ fk,
                          bf16* __restrict__ Aqo, bf16* __restrict__ Ako,
                          bf16* __restrict__ pqo, bf16* __restrict__ pko) {
    __shared__ float4 ps[128];
    const float* f = blockIdx.z ? fk : fq;
    bf16* A    = blockIdx.z ? Ako : Aqo;
    bf16* pool = blockIdx.z ? pko : pqo;
    int b = blockIdx.y;
    int half = threadIdx.x >> 7;                   // 0 or 1
    int cl = threadIdx.x & 127;
    int c4 = blockIdx.x * 128 + cl;                // 0..511
    const float4* p = (const float4*)(f + (size_t)b * HW * Cc) + c4;
    int i0 = half ? 25 : 0, i1 = half ? 49 : 25;
    float4 s = {0.f, 0.f, 0.f, 0.f};
    for (int i = i0; i < i1; i++) {
        float4 v = p[(size_t)i * (Cc / 4)];
        s.x += v.x; s.y += v.y; s.z += v.z; s.w += v.w;
        __nv_bfloat162 p0, p1;
        p0.x = __float2bfloat16(v.x); p0.y = __float2bfloat16(v.y);
        p1.x = __float2bfloat16(v.z); p1.y = __float2bfloat16(v.w);
        size_t o = ((size_t)b * HW + i) * Cc + c4 * 4;
        *(__nv_bfloat162*)&A[o]     = p0;
        *(__nv_bfloat162*)&A[o + 2] = p1;
    }
    if (half) ps[cl] = s;
    __syncthreads();
    if (!half) {
        float4 s2 = ps[cl];
        s.x += s2.x; s.y += s2.y; s.z += s2.z; s.w += s2.w;
        const float inv = 1.0f / 49.0f;
        __nv_bfloat162 q0, q1;
        q0.x = __float2bfloat16(s.x * inv); q0.y = __float2bfloat16(s.y * inv);
        q1.x = __float2bfloat16(s.z * inv); q1.y = __float2bfloat16(s.w * inv);
        size_t o = (size_t)b * Cc + c4 * 4;
        *(__nv_bfloat162*)&pool[o]     = q0;
        *(__nv_bfloat162*)&pool[o + 2] = q1;
    }
}

// ========================= op-table mma.sync GEMM (BK=64) ====================
// EPI 0: fp32 partial at op.Cf + kidx*op.M*N (no bias)
// EPI 1: bias+relu -> plain bf16 at op.Cb
// EPI 2: exp-rowsum -> op.Cf[blockIdx.x*op.M + row]
struct GOp { const bf16* A; const bf16* B; const float* bias; float* Cf; bf16* Cb; int M; };
struct GOps { GOp op[4]; };

#define ROWB 144
#define MATB (128*ROWB)         // 18432
#define STGB (2*MATB)           // 36864
#define SM_TOTAL (2*STGB)       // 73728

template<int EPI>
__global__ __launch_bounds__(256, 2)
void gemm_mma(GOps ops, int N, int ldA, int ldB, int nbC, int remC, int nzk, int yglob) {
    extern __shared__ char smem[];
    const uint32_t sb = smem_u32(smem);
    const int tid = threadIdx.x;
    const int wid = tid >> 5;
    const int lid = tid & 31;
    const int wm = wid >> 2;
    const int wn = wid & 3;
    const int g = lid >> 2;
    const int t = lid & 3;
    const int z = blockIdx.z;
    const int head = z / nzk;
    const int kidx = z - head * nzk;
    const bool isg = ((int)blockIdx.y == yglob);
    const GOp op = ops.op[(isg ? 2 : 0) + head];
    const int bm = isg ? 0 : blockIdx.y * 128;
    const int bn = blockIdx.x * 128;
    const int kbeg = (kidx * nbC + min(kidx, remC)) * 64;
    const int nch = nbC + (kidx < remC ? 1 : 0);

    const bf16* A = op.A + (size_t)bm * ldA + kbeg;
    const bf16* B = op.B + (size_t)bn * ldB + kbeg;

    const int r0 = tid >> 3, c0 = tid & 7;

    float acc[4][4][4];
#pragma unroll
    for (int i = 0; i < 4; i++)
#pragma unroll
        for (int j = 0; j < 4; j++)
#pragma unroll
            for (int c = 0; c < 4; c++) acc[i][j][c] = 0.f;

    // prologue: chunk 0 -> stage 0
#pragma unroll
    for (int s = 0; s < 4; s++) {
        int r = r0 + s * 32;
        cp16(sb + 0*MATB + r*ROWB + c0*16, A + (size_t)r * ldA + c0 * 8);
        cp16(sb + 1*MATB + r*ROWB + c0*16, B + (size_t)r * ldB + c0 * 8);
    }
    CP_COMMIT();

    const uint32_t a_lm = (uint32_t)((wm*64 + (lid & 7) + ((lid >> 3) & 1) * 8) * ROWB
                                     + ((lid >> 4) & 1) * 16);
    const uint32_t b_lm = (uint32_t)((wn*32 + (lid & 7) + ((lid >> 4) & 1) * 8) * ROWB
                                     + ((lid >> 3) & 1) * 16);

    for (int ch = 0; ch < nch; ch++) {
        CP_WAIT0();
        __syncthreads();
        if (ch + 1 < nch) {
            const int k0 = (ch + 1) * 64;
            uint32_t st = sb + ((ch + 1) & 1) * STGB;
#pragma unroll
            for (int s = 0; s < 4; s++) {
                int r = r0 + s * 32;
                cp16(st + 0*MATB + r*ROWB + c0*16, A + (size_t)r * ldA + k0 + c0 * 8);
                cp16(st + 1*MATB + r*ROWB + c0*16, B + (size_t)r * ldB + k0 + c0 * 8);
            }
            CP_COMMIT();
        }
        const uint32_t st = sb + (ch & 1) * STGB;
#pragma unroll
        for (int ks = 0; ks < 4; ks++) {
            const uint32_t koff = ks * 32;
            uint32_t ah[4][4];
#pragma unroll
            for (int i = 0; i < 4; i++) {
                uint32_t aa = st + a_lm + i * (16 * ROWB) + koff;
                LDMX4(ah[i][0], ah[i][1], ah[i][2], ah[i][3], aa);
            }
#pragma unroll
            for (int jp = 0; jp < 2; jp++) {
                uint32_t bh[2][2];
                uint32_t bb = st + 1*MATB + b_lm + jp * (16 * ROWB) + koff;
                LDMX4(bh[0][0], bh[0][1], bh[1][0], bh[1][1], bb);
#pragma unroll
                for (int i = 0; i < 4; i++)
#pragma unroll
                    for (int jj = 0; jj < 2; jj++)
                        mma16816(acc[i][jp*2 + jj], ah[i], bh[jj]);
            }
        }
        __syncthreads();
    }

    // ---- epilogue ----
    if (EPI == 2) {
        float rs[8];
#pragma unroll
        for (int i = 0; i < 4; i++)
#pragma unroll
            for (int h = 0; h < 2; h++) {
                float s = 0.f;
#pragma unroll
                for (int j = 0; j < 4; j++)
                    s += __expf(acc[i][j][2*h] * INV_TAU)
                       + __expf(acc[i][j][2*h + 1] * INV_TAU);
                s += __shfl_xor_sync(0xFFFFFFFFu, s, 1);
                s += __shfl_xor_sync(0xFFFFFFFFu, s, 2);
                rs[i*2 + h] = s;
            }
        float* sm = (float*)smem;
        __syncthreads();
        if (t == 0) {
#pragma unroll
            for (int idx = 0; idx < 8; idx++) {
                int i = idx >> 1, h = idx & 1;
                int row = wm*64 + i*16 + g + h*8;
                sm[row*4 + wn] = rs[idx];
            }
        }
        __syncthreads();
        if (tid < 128) {
            float tot = sm[tid*4+0] + sm[tid*4+1] + sm[tid*4+2] + sm[tid*4+3];
            op.Cf[(size_t)blockIdx.x * op.M + bm + tid] = tot;
        }
        return;
    }
#pragma unroll
    for (int i = 0; i < 4; i++) {
        int row0 = bm + wm*64 + i*16 + g;
#pragma unroll
        for (int j = 0; j < 4; j++) {
            int col = bn + wn*32 + j*8 + 2*t;
            float b0 = 0.f, b1 = 0.f;
            if (EPI == 1) { b0 = op.bias[col]; b1 = op.bias[col + 1]; }
#pragma unroll
            for (int h = 0; h < 2; h++) {
                int row = row0 + h*8;
                float v0 = acc[i][j][2*h]     + b0;
                float v1 = acc[i][j][2*h + 1] + b1;
                if (EPI == 1) {
                    v0 = fmaxf(v0, 0.f); v1 = fmaxf(v1, 0.f);
                    __nv_bfloat162 ph;
                    ph.x = __float2bfloat16(v0); ph.y = __float2bfloat16(v1);
                    *(__nv_bfloat162*)&op.Cb[(size_t)row * N + col] = ph;
                } else {              // EPI 0: fp32 partial at + kidx*M*N
                    size_t o = (size_t)kidx * op.M * N + (size_t)row * N + col;
                    float2 fv; fv.x = v0; fv.y = v1;
                    *(float2*)&op.Cf[o] = fv;
                }
            }
        }
    }
}

// ========================= fused reduce(4) + bias + l2norm ===================
struct NArgs {
    const float *pd0, *pd1, *pg0, *pg1;          // 4-slab partial bases
    const float *bd2, *mbd2, *bg2, *mbg2;
    float *qg, *kg, *qd, *kd;
    bf16 *qdm;
};

__global__ void l2norm_all(NArgs na) {
    int r = blockIdx.x * 8 + threadIdx.y;
    const float *pb, *bias;
    size_t slab;
    float* outx;
    bf16* mo = nullptr;
    if (r < Bn) {
        pb = na.pg0 + (size_t)r * De; slab = (size_t)Bn * De;
        bias = na.bg2; outx = na.qg + (size_t)r * De;
    } else if (r < 2*Bn) {
        int rr = r - Bn;
        pb = na.pg1 + (size_t)rr * De; slab = (size_t)Bn * De;
        bias = na.mbg2; outx = na.kg + (size_t)rr * De;
    } else if (r < 2*Bn + Nrow) {
        int rr = r - 2*Bn;
        pb = na.pd0 + (size_t)rr * De; slab = (size_t)Nrow * De;
        bias = na.bd2; outx = na.qd + (size_t)rr * De;
        mo = na.qdm + (size_t)rr * De;
    } else {
        int rr = r - 2*Bn - Nrow;
        pb = na.pd1 + (size_t)rr * De; slab = (size_t)Nrow * De;
        bias = na.mbd2; outx = na.kd + (size_t)rr * De;
    }
    int lane = threadIdx.x;
    float4 v = *(const float4*)(bias + lane * 4);
#pragma unroll
    for (int s = 0; s < 4; s++) {
        float4 a = *(const float4*)(pb + s * slab + lane * 4);
        v.x += a.x; v.y += a.y; v.z += a.z; v.w += a.w;
    }
    float ss = v.x*v.x + v.y*v.y + v.z*v.z + v.w*v.w;
#pragma unroll
    for (int o = 16; o; o >>= 1) ss += __shfl_xor_sync(0xFFFFFFFFu, ss, o);
    float rr = 1.0f / sqrtf(fmaxf(ss, 1e-12f));
    v.x *= rr; v.y *= rr; v.z *= rr; v.w *= rr;
    *(float4*)(outx + lane * 4) = v;
    if (mo) {
        __nv_bfloat162 p0b, p1b;
        p0b.x = __float2bfloat16(v.x); p0b.y = __float2bfloat16(v.y);
        p1b.x = __float2bfloat16(v.z); p1b.y = __float2bfloat16(v.w);
        *(__nv_bfloat162*)&mo[lane * 4]     = p0b;
        *(__nv_bfloat162*)&mo[lane * 4 + 2] = p1b;
    }
}

// ========================= merged lg + match =================================
__global__ void lg_match(const float* __restrict__ qg, const float* __restrict__ kg,
                         float* __restrict__ lgout,
                         const float* __restrict__ qd, const float* __restrict__ kd,
                         bf16* __restrict__ mt, float* __restrict__ pos) {
    __shared__ float qs[128];
    __shared__ float buf[128];
    __shared__ int s_idx;
    int t = threadIdx.x;
    if (blockIdx.x < Bn) {
        int row = blockIdx.x;
        qs[t] = qg[(size_t)row * De + t];
        __syncthreads();
        const float* kp = kg + (size_t)t * De;
        float dot = 0.f;
#pragma unroll 8
        for (int c = 0; c < De; c++) dot = fmaf(qs[c], kp[c], dot);
        float logit = dot * INV_TAU;
        buf[t] = __expf(logit); __syncthreads();
        for (int s = 64; s; s >>= 1) { if (t < s) buf[t] += buf[t + s]; __syncthreads(); }
        if (t == row) lgout[row] = logf(buf[0]) - logit;
    } else {
        int row = blockIdx.x - Bn;
        int b = row / HW;
        qs[t] = qd[(size_t)row * De + t];
        __syncthreads();
        if (t < HW) {
            const float* kp = kd + (size_t)(b * HW + t) * De;
            float d = 0.f;
#pragma unroll 8
            for (int c = 0; c < De; c++) d = fmaf(qs[c], kp[c], d);
            buf[t] = d;
        }
        __syncthreads();
        if (t == 0) {
            float bv = buf[0]; int bi = 0;
            for (int j = 1; j < HW; j++)
                if (buf[j] > bv) { bv = buf[j]; bi = j; }
            s_idx = bi; pos[row] = bv;
        }
        __syncthreads();
        mt[(size_t)row * De + t] = __float2bfloat16(kd[(size_t)(b * HW + s_idx) * De + t]);
    }
}

__global__ void lse_finish(const float* __restrict__ Spart, const float* __restrict__ pos,
                           float* __restrict__ out) {
    int row = blockIdx.x * 256 + threadIdx.x;
    if (row >= Nrow) return;
    float s = 0.f;
#pragma unroll
    for (int j = 0; j < NTILE; j++) s += Spart[(size_t)j * Nrow + row];
    out[row] = logf(s) - pos[row] * INV_TAU;
}

__global__ void final_kernel(const float* __restrict__ lg, const float* __restrict__ ld,
                             float* __restrict__ out) {
    int t = threadIdx.x;
    float s1 = 0.f, s2 = 0.f;
    if (t < Bn) s1 = lg[t];
    for (int j = t; j < Nrow; j += 256) s2 += ld[j];
    __shared__ float r1[256], r2[256];
    r1[t] = s1; r2[t] = s2; __syncthreads();
    for (int o = 128; o; o >>= 1) {
        if (t < o) { r1[t] += r1[t + o]; r2[t] += r2[t + o]; }
        __syncthreads();
    }
    if (t == 0) out[0] = 0.5f * (r1[0] / (float)Bn) + 0.5f * (r2[0] / (float)Nrow);
}

// ========================= host orchestration ================================
extern "C" void kernel_launch(void* const* d_in, const int* in_sizes, int n_in,
                              void* d_out, int out_size) {
    const float* feat_q = (const float*)d_in[0];
    const float* feat_k = (const float*)d_in[1];
    const float* Wg1  = (const float*)d_in[2];   const float* bg1 = (const float*)d_in[3];
    const float* Wg2  = (const float*)d_in[4];   const float* bg2 = (const float*)d_in[5];
    const float* Wd1  = (const float*)d_in[6];   const float* bd1 = (const float*)d_in[7];
    const float* Wd2  = (const float*)d_in[8];   const float* bd2 = (const float*)d_in[9];
    const float* mWg1 = (const float*)d_in[10];  const float* mbg1 = (const float*)d_in[11];
    const float* mWg2 = (const float*)d_in[12];  const float* mbg2 = (const float*)d_in[13];
    const float* mWd1 = (const float*)d_in[14];  const float* mbd1 = (const float*)d_in[15];
    const float* mWd2 = (const float*)d_in[16];  const float* mbd2 = (const float*)d_in[17];
    float* out = (float*)d_out;

    cudaFuncSetAttribute(gemm_mma<0>, cudaFuncAttributeMaxDynamicSharedMemorySize, SM_TOTAL);
    cudaFuncSetAttribute(gemm_mma<1>, cudaFuncAttributeMaxDynamicSharedMemorySize, SM_TOTAL);
    cudaFuncSetAttribute(gemm_mma<2>, cudaFuncAttributeMaxDynamicSharedMemorySize, SM_TOTAL);

#define SYM(p, s) cudaGetSymbolAddress((void**)&p, s)
    bf16 *Wd1T, *mWd1T, *Wg1T, *mWg1T, *Wg2T, *Wd2T, *mWg2T, *mWd2T;
    bf16 *Aq, *Ak, *pq, *pk, *gh, *hid, *qdm, *mt;
    float *part, *partG, *Spart, *qg, *kg, *qd, *kd, *pos, *lg, *ld;
    SYM(Wd1T, g_Wd1T); SYM(mWd1T, g_mWd1T); SYM(Wg1T, g_Wg1T); SYM(mWg1T, g_mWg1T);
    SYM(Wg2T, g_Wg2T); SYM(Wd2T, g_Wd2T); SYM(mWg2T, g_mWg2T); SYM(mWd2T, g_mWd2T);
    SYM(Aq, g_Aq); SYM(Ak, g_Ak); SYM(pq, g_pq); SYM(pk, g_pk);
    SYM(gh, g_gh); SYM(hid, g_hid); SYM(qdm, g_qdm); SYM(mt, g_mt);
    SYM(part, g_part); SYM(partG, g_partG); SYM(Spart, g_Spart);
    SYM(qg, g_qg); SYM(kg, g_kg); SYM(qd, g_qd); SYM(kd, g_kd);
    SYM(pos, g_pos); SYM(lg, g_lg); SYM(ld, g_ld);
#undef SYM

    // ---- 1. all weight transposes ----
    TP tp;
    tp.W[0] = Wd1;  tp.T[0] = Wd1T;
    tp.W[1] = mWd1; tp.T[1] = mWd1T;
    tp.W[2] = Wg1;  tp.T[2] = Wg1T;
    tp.W[3] = mWg1; tp.T[3] = mWg1T;
    tp.W[4] = Wg2;  tp.T[4] = Wg2T;
    tp.W[5] = Wd2;  tp.T[5] = Wd2T;
    tp.W[6] = mWg2; tp.T[6] = mWg2T;
    tp.W[7] = mWd2; tp.T[7] = mWd2T;
    transpose_all<<<8704, dim3(32, 8)>>>(tp);

    // ---- 2. activations (HW-split) ----
    feat_prep<<<dim3(4, Bn, 2), 256>>>(feat_q, feat_k, Aq, Ak, pq, pk);

    // ---- 3. L1 merged: dense (y<49) + global (y==49), full-K, bias+relu bf16 ----
    {
        GOps o;
        o.op[0] = { Aq, Wd1T,  bd1,  nullptr, hid,                   Nrow };
        o.op[1] = { Ak, mWd1T, mbd1, nullptr, hid + (size_t)Nrow*Dh, Nrow };
        o.op[2] = { pq, Wg1T,  bg1,  nullptr, gh,                    Bn };
        o.op[3] = { pk, mWg1T, mbg1, nullptr, gh + (size_t)Bn*Dh,    Bn };
        gemm_mma<1><<<dim3(Dh/128, NTILE + 1, 2), 256, SM_TOTAL>>>(
            o, Dh, Cc, Cc, 32, 0, 1, NTILE);
    }

    // ---- 4. L2 merged: down-proj + global L2, split-K 4 (partials) ----
    {
        GOps o;
        o.op[0] = { hid,                   Wd2T,  nullptr, part,                     nullptr, Nrow };
        o.op[1] = { hid + (size_t)Nrow*Dh, mWd2T, nullptr, part + 4*(size_t)Nrow*De, nullptr, Nrow };
        o.op[2] = { gh,                    Wg2T,  nullptr, partG,                    nullptr, Bn };
        o.op[3] = { gh + (size_t)Bn*Dh,    mWg2T, nullptr, partG + 4*(size_t)Bn*De,  nullptr, Bn };
        gemm_mma<0><<<dim3(1, NTILE + 1, 8), 256, SM_TOTAL>>>(
            o, De, Dh, Dh, 8, 0, 4, NTILE);
    }

    // ---- 5. fused reduce(4) + bias + l2norm ----
    {
        NArgs na;
        na.pd0 = part;  na.pd1 = part + 4*(size_t)Nrow*De;
        na.pg0 = partG; na.pg1 = partG + 4*(size_t)Bn*De;
        na.bd2 = bd2; na.mbd2 = mbd2; na.bg2 = bg2; na.mbg2 = mbg2;
        na.qg = qg; na.kg = kg; na.qd = qd; na.kd = kd; na.qdm = qdm;
        l2norm_all<<<(2*Bn + 2*Nrow)/8, dim3(32, 8)>>>(na);
    }

    // ---- 6. merged lg + match ----
    lg_match<<<Bn + Nrow, 128>>>(qg, kg, lg, qd, kd, mt, pos);

    // ---- 7. S-GEMM with fused exp epilogue (K=128 -> 2 chunks) ----
    {
        GOps o;
        o.op[0] = { qdm, mt, nullptr, Spart, nullptr, Nrow };
        o.op[1] = o.op[0]; o.op[2] = o.op[0]; o.op[3] = o.op[0];
        gemm_mma<2><<<dim3(NTILE, NTILE, 1), 256, SM_TOTAL>>>(
            o, Nrow, De, De, 2, 0, 1, -1);
    }

    // ---- 8/9. finish ----
    lse_finish<<<(Nrow + 255)/256, 256>>>(Spart, pos, ld);
    final_kernel<<<1, 256>>>(lg, ld, out);
}